// round 12
// baseline (speedup 1.0000x reference)
#include <cuda_runtime.h>
#include <cuda_bf16.h>
#include <cstdint>
#include <math.h>

#define EPS_BN 1e-5f

// ===========================================================================
// scratch (device globals)
// ===========================================================================
__device__ uint32_t g_seq [8388608];      // rows-seq hl NHWC; later cols fp32 (cast)
__device__ float    g_xg  [33554432];     // 32768 x 1024
__device__ float    g_rows[8388608];      // rows-LSTM out fp32 [b][w][h][c]
__device__ uint32_t g_rows_hl[8388608];   // hl-packed copy of g_rows
__device__ uint32_t g_cols_hl[8388608];   // cols-LSTM out NHWC hl
__device__ uint32_t g_hlB[8388608];       // conv temps, NHWC hl
__device__ uint32_t g_hlC[8388608];
__device__ uint32_t g_hlD[4194304];       // 128-channel temp
__device__ __nv_bfloat16 g_wb[11206656];  // conv weights: [ot][tap][cc][pass][k64][n128]
__device__ __nv_bfloat16 g_wih_frag[1048576]; // xg-GEMM B: [nt8][cc8][pass2][k64][n128]
__device__ float    g_whhT[2][65536];     // [dir][k][gate]
__device__ float    g_bias2[2][512];

// wb region offsets (elements)
#define WB_A 0u
#define WB_B 2359296u
#define WB_C 4718592u
#define WB_E 9437184u
#define WB_F 10616832u

// ===========================================================================
// mma.sync / ldmatrix helpers
// ===========================================================================
__device__ __forceinline__ uint32_t smem_u32(const void* p) {
    uint32_t a;
    asm("{ .reg .u64 t; cvta.to.shared.u64 t, %1; cvt.u32.u64 %0, t; }" : "=r"(a) : "l"(p));
    return a;
}
__device__ __forceinline__ void ldsm4(uint32_t* r, uint32_t addr) {
    asm volatile("ldmatrix.sync.aligned.m8n8.x4.shared.b16 {%0,%1,%2,%3}, [%4];"
        : "=r"(r[0]), "=r"(r[1]), "=r"(r[2]), "=r"(r[3]) : "r"(addr));
}
__device__ __forceinline__ void ldsm4t(uint32_t* r, uint32_t addr) {
    asm volatile("ldmatrix.sync.aligned.m8n8.x4.trans.shared.b16 {%0,%1,%2,%3}, [%4];"
        : "=r"(r[0]), "=r"(r[1]), "=r"(r[2]), "=r"(r[3]) : "r"(addr));
}
__device__ __forceinline__ void mma16816(float* c, const uint32_t* a, uint32_t b0, uint32_t b1) {
    asm volatile("mma.sync.aligned.m16n8k16.row.col.f32.bf16.bf16.f32 "
        "{%0,%1,%2,%3}, {%4,%5,%6,%7}, {%8,%9}, {%0,%1,%2,%3};"
        : "+f"(c[0]), "+f"(c[1]), "+f"(c[2]), "+f"(c[3])
        : "r"(a[0]), "r"(a[1]), "r"(a[2]), "r"(a[3]), "r"(b0), "r"(b1));
}
__device__ __forceinline__ uint32_t hl_pack(float v) {
    __nv_bfloat16 hi = __float2bfloat16(v);
    __nv_bfloat16 lo = __float2bfloat16(v - __bfloat162float(hi));
    return (uint32_t)__bfloat16_as_ushort(hi) | ((uint32_t)__bfloat16_as_ushort(lo) << 16);
}

// ===========================================================================
// prep: Whh transpose, bias sums, conv weight tiles
// ===========================================================================
__global__ void prep_kernel(const float* __restrict__ whh_f, const float* __restrict__ whh_b,
                            const float* __restrict__ bih_f, const float* __restrict__ bhh_f,
                            const float* __restrict__ bih_b, const float* __restrict__ bhh_b,
                            const float* __restrict__ c2w1, const float* __restrict__ c2w2,
                            const float* __restrict__ cvw1, const float* __restrict__ cvw2)
{
    unsigned i = blockIdx.x * 256u + threadIdx.x;
    if (i < 512u * 128u) {
        int g = i / 128, k = i % 128;
        g_whhT[0][k * 512 + g] = whh_f[i];
        g_whhT[1][k * 512 + g] = whh_b[i];
    }
    if (i < 512u) {
        g_bias2[0][i] = bih_f[i] + bhh_f[i];
        g_bias2[1][i] = bih_b[i] + bhh_b[i];
    }
    if (i < 11206656u) {
        unsigned l; int CC; int kind;
        if      (i < WB_B) { l = i - WB_A; CC = 8;  kind = 0; }
        else if (i < WB_C) { l = i - WB_B; CC = 8;  kind = 1; }
        else if (i < WB_E) { l = i - WB_C; CC = 16; kind = 2; }
        else if (i < WB_F) { l = i - WB_E; CC = 8;  kind = 3; }
        else               { l = i - WB_F; CC = 4;  kind = 4; }
        int n    = l & 127;
        int k    = (l >> 7) & 63;
        int pass = (l >> 13) & 1;
        unsigned q = l >> 14;
        int cc  = q % CC;  q /= CC;
        int tap = q % 9;   q /= 9;
        int ot  = q;
        int c  = cc * 32 + (k >> 1);
        int oc = ot * 128 + n;
        int odd = k & 1;
        float w;
        if      (kind == 0) w = c2w1[((size_t)oc * 512 + c) * 9 + tap]
                              + c2w1[((size_t)oc * 512 + c + 256) * 9 + tap];
        else if (kind == 1) w = c2w2[((size_t)oc * 256 + c) * 9 + tap];
        else if (kind == 2) w = c2w1[((size_t)oc * 512 + c) * 9 + tap];
        else if (kind == 3) w = cvw1[((size_t)oc * 256 + c) * 9 + tap];
        else                w = cvw2[((size_t)oc * 128 + c) * 9 + tap];
        __nv_bfloat16 hi = __float2bfloat16(w);
        __nv_bfloat16 val;
        if (pass == 0) val = hi;
        else val = odd ? __float2bfloat16(0.f)
                       : __float2bfloat16(w - __bfloat162float(hi));
        g_wb[i] = val;
    }
}

// xg-GEMM B fragments: [nt][cc][pass][k][n]; nt 0-3 = fwd gates, 4-7 = bwd
__global__ void prep2_kernel(const float* __restrict__ wih_f,
                             const float* __restrict__ wih_b)
{
    unsigned i = blockIdx.x * 256u + threadIdx.x;
    if (i >= 1048576u) return;
    int n    = i & 127;
    int k    = (i >> 7) & 63;
    int pass = (i >> 13) & 1;
    int cc   = (i >> 14) & 7;
    int nt   = (int)(i >> 17);
    int c    = cc * 32 + (k >> 1);
    int odd  = k & 1;
    const float* W = (nt >= 4) ? wih_b : wih_f;
    int gate = (nt & 3) * 128 + n;
    float w = W[gate * 256 + c];
    __nv_bfloat16 hi = __float2bfloat16(w);
    __nv_bfloat16 val;
    if (pass == 0) val = hi;
    else val = odd ? __float2bfloat16(0.f)
                   : __float2bfloat16(w - __bfloat162float(hi));
    g_wih_frag[i] = val;
}

// pack fp32 -> hl uint32
__global__ __launch_bounds__(256) void pack_hl_kernel(const float* __restrict__ in,
                                                      uint32_t* __restrict__ out, int n)
{
    int i = blockIdx.x * 1024 + threadIdx.x * 4;
    if (i + 3 < n) {
        float4 v = *(const float4*)(in + i);
        uint4 o;
        o.x = hl_pack(v.x); o.y = hl_pack(v.y);
        o.z = hl_pack(v.z); o.w = hl_pack(v.w);
        *(uint4*)(out + i) = o;
    }
}

// ===========================================================================
// build rows-sequence (upsample + concat) -> hl-packed NHWC
// ===========================================================================
__global__ __launch_bounds__(256) void build_seq_kernel(const float* __restrict__ x2,
                                                        const float* __restrict__ x1)
{
    __shared__ float sh[32][65];
    int bh = blockIdx.x;
    int b = bh >> 6, h = bh & 63;
    int ct = blockIdx.y;
    int c0 = ct * 32;
    int tid = threadIdx.x;

    if (ct < 4) {
        for (int idx = tid; idx < 32 * 64; idx += 256) {
            int ci = idx >> 6, w = idx & 63;
            sh[ci][w] = x2[(((size_t)b * 128 + (c0 + ci)) * 64 + h) * 64 + w];
        }
    } else {
        int cc0 = c0 - 128;
        float py = (float)h * 31.0f / 63.0f;
        int yl = (int)floorf(py);
        float wy = py - (float)yl;
        int yh = min(yl + 1, 31);
        for (int idx = tid; idx < 32 * 64; idx += 256) {
            int ci = idx >> 6, w = idx & 63;
            float px = (float)w * 31.0f / 63.0f;
            int xl = (int)floorf(px);
            float wx = px - (float)xl;
            int xh = min(xl + 1, 31);
            const float* base = x1 + ((size_t)b * 128 + (cc0 + ci)) * 1024;
            float v00 = base[yl * 32 + xl], v01 = base[yl * 32 + xh];
            float v10 = base[yh * 32 + xl], v11 = base[yh * 32 + xh];
            float v0 = v00 * (1.f - wx) + v01 * wx;
            float v1 = v10 * (1.f - wx) + v11 * wx;
            sh[ci][w] = v0 * (1.f - wy) + v1 * wy;
        }
    }
    __syncthreads();
    for (int idx = tid; idx < 32 * 64; idx += 256) {
        int w = idx >> 5, cl = idx & 31;
        g_seq[((size_t)bh * 64 + w) * 256 + c0 + cl] = hl_pack(sh[cl][w]);
    }
}

// ===========================================================================
// xg GEMM via mma: xg[32768,1024] = A_hl[32768,256ch] @ wih_frag + bias.
// CTA: 128 rows x 128 gates (blockIdx.y = nt). 256 threads = 8 warps (4Mx2N).
// ===========================================================================
#define GA_BYTES (128 * 144)
#define GB_BYTES (64 * 272)
#define G_SMEM   (GA_BYTES + 2 * GB_BYTES)

__global__ __launch_bounds__(256, 2) void gemm_mma_kernel(const uint32_t* __restrict__ Ahl)
{
    extern __shared__ __align__(16) char smem[];
    char* a_sh = smem;
    char* b_sh = smem + GA_BYTES;

    int tid = threadIdx.x;
    int lane = tid & 31, wid = tid >> 5;
    int warp_m = wid & 3, warp_n = wid >> 2;
    int mbase = blockIdx.x * 128;
    int nt = blockIdx.y;
    int dir = nt >> 2;
    int gbase = (nt & 3) * 128;

    float acc[2][8][4];
#pragma unroll
    for (int m = 0; m < 2; m++)
#pragma unroll
        for (int j = 0; j < 8; j++)
#pragma unroll
            for (int q = 0; q < 4; q++) acc[m][j][q] = 0.f;

    uint32_t a_base = smem_u32(a_sh);
    uint32_t b_base = smem_u32(b_sh);

    int arow = warp_m * 32 + (lane & 7) + ((lane >> 3) & 1) * 8;
    uint32_t a_addr0 = a_base + arow * 144 + ((lane >> 4) * 16);
    int brow = (lane & 7) + ((lane >> 3) & 1) * 8;
    int bcol = warp_n * 64 + ((lane >> 4) * 8);
    uint32_t b_addr0 = b_base + brow * 272 + bcol * 2;

    int s_px = tid >> 1, s_half = tid & 1;

    for (int cc = 0; cc < 8; cc++) {
        {
            const uint4* src = (const uint4*)(Ahl + ((size_t)(mbase + s_px)) * 256 + cc * 32 + s_half * 16);
            uint4* dst = (uint4*)(a_sh + s_px * 144 + s_half * 64);
#pragma unroll
            for (int i = 0; i < 4; i++) dst[i] = src[i];
        }
        const uint4* wsrc = (const uint4*)(g_wih_frag + ((size_t)(nt * 8 + cc)) * 16384u);
#pragma unroll
        for (int i = 0; i < 8; i++) {
            int idx = tid + i * 256;
            int pofs = (idx >= 1024) ? GB_BYTES : 0;
            int li = idx & 1023;
            *(uint4*)(b_sh + pofs + (li >> 4) * 272 + (li & 15) * 16) = wsrc[idx];
        }
        __syncthreads();
#pragma unroll
        for (int pass = 0; pass < 2; pass++) {
            uint32_t bp = b_addr0 + pass * GB_BYTES;
#pragma unroll
            for (int ksub = 0; ksub < 4; ksub++) {
                uint32_t a0[4], a1[4];
                ldsm4(a0, a_addr0 + ksub * 32);
                ldsm4(a1, a_addr0 + 16 * 144 + ksub * 32);
                uint32_t bfr[4][4];
#pragma unroll
                for (int p = 0; p < 4; p++)
                    ldsm4t(bfr[p], bp + ksub * 16 * 272 + p * 32);
#pragma unroll
                for (int j = 0; j < 8; j++) {
                    uint32_t bq0 = bfr[j >> 1][(j & 1) * 2];
                    uint32_t bq1 = bfr[j >> 1][(j & 1) * 2 + 1];
                    mma16816(acc[0][j], a0, bq0, bq1);
                    mma16816(acc[1][j], a1, bq0, bq1);
                }
            }
        }
        __syncthreads();
    }

#pragma unroll
    for (int m = 0; m < 2; m++) {
        int px0 = warp_m * 32 + m * 16 + (lane >> 2);
#pragma unroll
        for (int j = 0; j < 8; j++) {
            int oc = warp_n * 64 + j * 8 + (lane & 3) * 2;
            float b0 = g_bias2[dir][gbase + oc];
            float b1 = g_bias2[dir][gbase + oc + 1];
            size_t col = (size_t)dir * 512 + gbase + oc;
            float* r0 = &g_xg[(size_t)(mbase + px0) * 1024 + col];
            float* r1 = &g_xg[(size_t)(mbase + px0 + 8) * 1024 + col];
            *(float2*)r0 = make_float2(acc[m][j][0] + b0, acc[m][j][1] + b1);
            *(float2*)r1 = make_float2(acc[m][j][2] + b0, acc[m][j][3] + b1);
        }
    }
}

// ===========================================================================
// LSTM recurrence: EXACT R1 codegen shape (global-symbol stores, mode branch).
// 128 blocks (dir = blk>>6), 8 seqs/block, 256 threads, 64 steps inside.
// Both modes store fp32 with the SAME index formula; mode picks the buffer.
// ===========================================================================
__global__ __launch_bounds__(256) void lstm_kernel(int mode)
{
    int dir = blockIdx.x >> 6;
    int blk = blockIdx.x & 63;
    const float* whhT = g_whhT[dir];
    const float* xg = g_xg + dir * 512;
    float* out = mode ? (float*)g_seq : g_rows;

    __shared__ __align__(16) float h_sh[8][132];
    __shared__ __align__(16) float g_sh[8][516];

    int tid = threadIdx.x;
    int ts = tid >> 7;
    int tg = tid & 127;
    int g0 = tg * 4;
    int s_base = ts * 4;
    int base_n = blk * 8;

    float c_reg[4] = {0.f, 0.f, 0.f, 0.f};

    for (int t = 0; t < 64; t++) {
        int ta = dir ? (63 - t) : t;
        float acc[4][4];
#pragma unroll
        for (int si = 0; si < 4; si++) {
            int n = base_n + s_base + si;
            float4 v = *(const float4*)&xg[((size_t)n * 64 + ta) * 1024 + g0];
            acc[si][0] = v.x; acc[si][1] = v.y; acc[si][2] = v.z; acc[si][3] = v.w;
        }
        if (t > 0) {
#pragma unroll 4
            for (int k = 0; k < 128; k++) {
                float4 w = *(const float4*)&whhT[(k << 9) + g0];
                float h0 = h_sh[s_base + 0][k];
                float h1 = h_sh[s_base + 1][k];
                float h2 = h_sh[s_base + 2][k];
                float h3 = h_sh[s_base + 3][k];
                acc[0][0] += h0 * w.x; acc[0][1] += h0 * w.y; acc[0][2] += h0 * w.z; acc[0][3] += h0 * w.w;
                acc[1][0] += h1 * w.x; acc[1][1] += h1 * w.y; acc[1][2] += h1 * w.z; acc[1][3] += h1 * w.w;
                acc[2][0] += h2 * w.x; acc[2][1] += h2 * w.y; acc[2][2] += h2 * w.z; acc[2][3] += h2 * w.w;
                acc[3][0] += h3 * w.x; acc[3][1] += h3 * w.y; acc[3][2] += h3 * w.z; acc[3][3] += h3 * w.w;
            }
        }
#pragma unroll
        for (int si = 0; si < 4; si++) {
            *(float4*)&g_sh[s_base + si][g0] =
                make_float4(acc[si][0], acc[si][1], acc[si][2], acc[si][3]);
        }
        __syncthreads();
#pragma unroll
        for (int p = 0; p < 4; p++) {
            int idx = tid + p * 256;
            int s = idx >> 7, j = idx & 127;
            float iv = g_sh[s][j];
            float fv = g_sh[s][128 + j];
            float gv = g_sh[s][256 + j];
            float ov = g_sh[s][384 + j];
            float ig = 1.f / (1.f + expf(-iv));
            float fg = 1.f / (1.f + expf(-fv));
            float og = 1.f / (1.f + expf(-ov));
            c_reg[p] = fg * c_reg[p] + ig * tanhf(gv);
            float h = og * tanhf(c_reg[p]);
            h_sh[s][j] = h;
            int n = base_n + s;
            int b = n >> 6, loc = n & 63;
            out[(((size_t)(b * 64 + ta)) * 64 + loc) * 256 + dir * 128 + j] = h;
        }
        __syncthreads();
    }
}

// ===========================================================================
// mma.sync bf16 implicit-GEMM 3x3 conv (R8 version — best measured).
// ===========================================================================
#define CONV_A_BYTES   (128 * 144)
#define CONV_B_BYTES   (64 * 272)
#define CONV_SMEM      (CONV_A_BYTES + 2 * CONV_B_BYTES)

__global__ __launch_bounds__(256, 2) void conv_mma_kernel(
    const uint32_t* __restrict__ in0, int C0,
    const uint32_t* __restrict__ in1, int C1,
    unsigned wb_off,
    const float* __restrict__ gamma, const float* __restrict__ beta,
    void* outp, int OC, int final_nchw)
{
    extern __shared__ __align__(16) char smem[];
    char* a_sh = smem;
    char* b_sh = smem + CONV_A_BYTES;
    __shared__ float scs[128], bbs[128];

    int tid = threadIdx.x;
    int lane = tid & 31, wid = tid >> 5;
    int warp_m = wid & 3, warp_n = wid >> 2;
    int bx = blockIdx.x;
    int b = bx >> 5, y0 = (bx & 31) * 2;
    int ot = blockIdx.y, ocb = ot * 128;
    int CIN = C0 + C1, CC = CIN >> 5;

    if (tid < 128) {
        scs[tid] = gamma[ocb + tid] * rsqrtf(1.f + EPS_BN);
        bbs[tid] = beta[ocb + tid];
    }

    float acc[2][8][4];
#pragma unroll
    for (int m = 0; m < 2; m++)
#pragma unroll
        for (int j = 0; j < 8; j++)
#pragma unroll
            for (int q = 0; q < 4; q++) acc[m][j][q] = 0.f;

    uint32_t a_base = smem_u32(a_sh);
    uint32_t b_base = smem_u32(b_sh);

    int arow = warp_m * 32 + (lane & 7) + ((lane >> 3) & 1) * 8;
    uint32_t a_addr0 = a_base + arow * 144 + ((lane >> 4) * 16);
    int brow = (lane & 7) + ((lane >> 3) & 1) * 8;
    int bcol = warp_n * 64 + ((lane >> 4) * 8);
    uint32_t b_addr0 = b_base + brow * 272 + bcol * 2;

    int s_px = tid >> 1, s_half = tid & 1;
    int s_yo = s_px >> 6, s_x = s_px & 63;

    for (int tap = 0; tap < 9; tap++) {
        int ty = tap / 3 - 1, tx = tap % 3 - 1;
        int ys = y0 + s_yo + ty;
        int xs = s_x + tx;
        bool ok = ((unsigned)ys < 64u) && ((unsigned)xs < 64u);
        for (int cc = 0; cc < CC; cc++) {
            {
                int c0 = cc * 32 + s_half * 16;
                const uint4* src;
                if (c0 < C0) src = (const uint4*)(in0 + ((size_t)((b * 64 + ys) * 64 + xs)) * C0 + c0);
                else         src = (const uint4*)(in1 + ((size_t)((b * 64 + ys) * 64 + xs)) * C1 + (c0 - C0));
                uint4* dst = (uint4*)(a_sh + s_px * 144 + s_half * 64);
#pragma unroll
                for (int i = 0; i < 4; i++) {
                    uint4 v = make_uint4(0u, 0u, 0u, 0u);
                    if (ok) v = src[i];
                    dst[i] = v;
                }
            }
            const uint4* wsrc = (const uint4*)(g_wb + wb_off +
                ((size_t)((ot * 9 + tap) * CC + cc)) * 16384u);
#pragma unroll
            for (int i = 0; i < 8; i++) {
                int idx = tid + i * 256;
                int pofs = (idx >= 1024) ? CONV_B_BYTES : 0;
                int li = idx & 1023;
                *(uint4*)(b_sh + pofs + (li >> 4) * 272 + (li & 15) * 16) = wsrc[idx];
            }
            __syncthreads();
#pragma unroll
            for (int pass = 0; pass < 2; pass++) {
                uint32_t bp = b_addr0 + pass * CONV_B_BYTES;
#pragma unroll
                for (int ksub = 0; ksub < 4; ksub++) {
                    uint32_t a0[4], a1[4];
                    ldsm4(a0, a_addr0 + ksub * 32);
                    ldsm4(a1, a_addr0 + 16 * 144 + ksub * 32);
                    uint32_t bfr[4][4];
#pragma unroll
                    for (int p = 0; p < 4; p++)
                        ldsm4t(bfr[p], bp + ksub * 16 * 272 + p * 32);
#pragma unroll
                    for (int j = 0; j < 8; j++) {
                        uint32_t bq0 = bfr[j >> 1][(j & 1) * 2];
                        uint32_t bq1 = bfr[j >> 1][(j & 1) * 2 + 1];
                        mma16816(acc[0][j], a0, bq0, bq1);
                        mma16816(acc[1][j], a1, bq0, bq1);
                    }
                }
            }
            __syncthreads();
        }
    }

#pragma unroll
    for (int m = 0; m < 2; m++) {
        int px0 = warp_m * 32 + m * 16 + (lane >> 2);
#pragma unroll
        for (int j = 0; j < 8; j++) {
            int oc = warp_n * 64 + j * 8 + (lane & 3) * 2;
            float sc0 = scs[oc], sc1 = scs[oc + 1];
            float bb0 = bbs[oc], bb1 = bbs[oc + 1];
            float v00 = fmaxf(fmaf(acc[m][j][0], sc0, bb0), 0.f);
            float v01 = fmaxf(fmaf(acc[m][j][1], sc1, bb1), 0.f);
            float v10 = fmaxf(fmaf(acc[m][j][2], sc0, bb0), 0.f);
            float v11 = fmaxf(fmaf(acc[m][j][3], sc1, bb1), 0.f);
            if (!final_nchw) {
                uint32_t* out = (uint32_t*)outp;
                size_t base0 = ((size_t)((b * 64 + (y0 + (px0 >> 6))) * 64 + (px0 & 63))) * OC + ocb + oc;
                int px1 = px0 + 8;
                size_t base1 = ((size_t)((b * 64 + (y0 + (px1 >> 6))) * 64 + (px1 & 63))) * OC + ocb + oc;
                *(uint2*)(out + base0) = make_uint2(hl_pack(v00), hl_pack(v01));
                *(uint2*)(out + base1) = make_uint2(hl_pack(v10), hl_pack(v11));
            } else {
                float* out = (float*)outp;
                size_t r0 = ((size_t)b * OC + ocb + oc) * 4096 + y0 * 64;
                size_t r1 = ((size_t)b * OC + ocb + oc + 1) * 4096 + y0 * 64;
                out[r0 + px0] = v00;
                out[r1 + px0] = v01;
                out[r0 + px0 + 8] = v10;
                out[r1 + px0 + 8] = v11;
            }
        }
    }
}

// ===========================================================================
// launcher
// ===========================================================================
extern "C" void kernel_launch(void* const* d_in, const int* in_sizes, int n_in,
                              void* d_out, int out_size)
{
    const float* x1    = (const float*)d_in[0];
    const float* x2    = (const float*)d_in[1];
    const float* wih_f = (const float*)d_in[2];
    const float* whh_f = (const float*)d_in[3];
    const float* bih_f = (const float*)d_in[4];
    const float* bhh_f = (const float*)d_in[5];
    const float* wih_b = (const float*)d_in[6];
    const float* whh_b = (const float*)d_in[7];
    const float* bih_b = (const float*)d_in[8];
    const float* bhh_b = (const float*)d_in[9];
    const float* c2_w1 = (const float*)d_in[10];
    const float* c2_g1 = (const float*)d_in[11];
    const float* c2_b1 = (const float*)d_in[12];
    const float* c2_w2 = (const float*)d_in[13];
    const float* c2_g2 = (const float*)d_in[14];
    const float* c2_b2 = (const float*)d_in[15];
    const float* cv_w1 = (const float*)d_in[16];
    const float* cv_g1 = (const float*)d_in[17];
    const float* cv_b1 = (const float*)d_in[18];
    const float* cv_w2 = (const float*)d_in[19];
    const float* cv_g2 = (const float*)d_in[20];
    const float* cv_b2 = (const float*)d_in[21];

    uint32_t *p_seq = nullptr, *p_rows_hl = nullptr, *p_cols = nullptr,
             *p_hlB = nullptr, *p_hlC = nullptr, *p_hlD = nullptr;
    float *p_rows = nullptr;
    cudaGetSymbolAddress((void**)&p_seq, g_seq);
    cudaGetSymbolAddress((void**)&p_rows, g_rows);
    cudaGetSymbolAddress((void**)&p_rows_hl, g_rows_hl);
    cudaGetSymbolAddress((void**)&p_cols, g_cols_hl);
    cudaGetSymbolAddress((void**)&p_hlB, g_hlB);
    cudaGetSymbolAddress((void**)&p_hlC, g_hlC);
    cudaGetSymbolAddress((void**)&p_hlD, g_hlD);

    cudaFuncSetAttribute(conv_mma_kernel,
                         cudaFuncAttributeMaxDynamicSharedMemorySize, CONV_SMEM);
    cudaFuncSetAttribute(gemm_mma_kernel,
                         cudaFuncAttributeMaxDynamicSharedMemorySize, G_SMEM);

    prep_kernel<<<43776, 256>>>(whh_f, whh_b, bih_f, bhh_f, bih_b, bhh_b,
                                c2_w1, c2_w2, cv_w1, cv_w2);
    prep2_kernel<<<4096, 256>>>(wih_f, wih_b);
    build_seq_kernel<<<dim3(512, 8), 256>>>(x2, x1);

    // rows pass
    gemm_mma_kernel<<<dim3(256, 8), 256, G_SMEM>>>(p_seq);
    lstm_kernel<<<128, 256>>>(0);
    pack_hl_kernel<<<8192, 256>>>(p_rows, p_rows_hl, 8388608);

    // cols pass (cols fp32 reuses g_seq storage)
    gemm_mma_kernel<<<dim3(256, 8), 256, G_SMEM>>>(p_rows_hl);
    lstm_kernel<<<128, 256>>>(1);
    pack_hl_kernel<<<8192, 256>>>((const float*)p_seq, p_cols, 8388608);

    // x_site = double_conv(concat([x,x])) via folded weights (A), then c2_w2 (B)
    conv_mma_kernel<<<dim3(256, 2), 256, CONV_SMEM>>>(p_cols, 256, nullptr, 0, WB_A,
                                                      c2_g1, c2_b1, p_hlB, 256, 0);
    conv_mma_kernel<<<dim3(256, 2), 256, CONV_SMEM>>>(p_hlB, 256, nullptr, 0, WB_B,
                                                      c2_g2, c2_b2, p_hlC, 256, 0);
    // x = double_conv(concat([x, x_site]))
    conv_mma_kernel<<<dim3(256, 2), 256, CONV_SMEM>>>(p_cols, 256, p_hlC, 256, WB_C,
                                                      c2_g1, c2_b1, p_hlB, 256, 0);
    conv_mma_kernel<<<dim3(256, 2), 256, CONV_SMEM>>>(p_hlB, 256, nullptr, 0, WB_B,
                                                      c2_g2, c2_b2, p_hlC, 256, 0);
    // final double_conv (cv): 256->128, 128->128 -> d_out (fp32 NCHW)
    conv_mma_kernel<<<dim3(256, 1), 256, CONV_SMEM>>>(p_hlC, 256, nullptr, 0, WB_E,
                                                      cv_g1, cv_b1, p_hlD, 128, 0);
    conv_mma_kernel<<<dim3(256, 1), 256, CONV_SMEM>>>(p_hlD, 128, nullptr, 0, WB_F,
                                                      cv_g2, cv_b2, d_out, 128, 1);
}

// round 13
// speedup vs baseline: 1.1746x; 1.1746x over previous
#include <cuda_runtime.h>
#include <cuda_bf16.h>
#include <cstdint>
#include <math.h>

#define EPS_BN 1e-5f

// ===========================================================================
// scratch (device globals)
// ===========================================================================
__device__ uint32_t g_seq [8388608];      // rows-seq hl NHWC
__device__ float    g_xg  [33554432];     // 32768 x 1024
__device__ uint32_t g_rows_hl[8388608];   // rows-LSTM out hl [b][w][h][c]
__device__ uint32_t g_cols_hl[8388608];   // cols-LSTM out NHWC hl
__device__ uint32_t g_hlB[8388608];       // conv temps, NHWC hl
__device__ uint32_t g_hlC[8388608];
__device__ uint32_t g_hlD[4194304];       // 128-channel temp
__device__ __nv_bfloat16 g_wb[11206656];  // conv weights: [ot][tap][cc][pass][k64][n128]
__device__ __nv_bfloat16 g_wih_frag[1048576]; // xg-GEMM B: [nt8][cc8][pass2][k64][n128]
__device__ float    g_whhT[2][65536];     // [dir][k][gate]
__device__ float    g_bias2[2][512];

// wb region offsets (elements)
#define WB_A 0u
#define WB_B 2359296u
#define WB_C 4718592u
#define WB_E 9437184u
#define WB_F 10616832u

// ===========================================================================
// mma.sync / ldmatrix helpers
// ===========================================================================
__device__ __forceinline__ uint32_t smem_u32(const void* p) {
    uint32_t a;
    asm("{ .reg .u64 t; cvta.to.shared.u64 t, %1; cvt.u32.u64 %0, t; }" : "=r"(a) : "l"(p));
    return a;
}
__device__ __forceinline__ void ldsm4(uint32_t* r, uint32_t addr) {
    asm volatile("ldmatrix.sync.aligned.m8n8.x4.shared.b16 {%0,%1,%2,%3}, [%4];"
        : "=r"(r[0]), "=r"(r[1]), "=r"(r[2]), "=r"(r[3]) : "r"(addr));
}
__device__ __forceinline__ void ldsm4t(uint32_t* r, uint32_t addr) {
    asm volatile("ldmatrix.sync.aligned.m8n8.x4.trans.shared.b16 {%0,%1,%2,%3}, [%4];"
        : "=r"(r[0]), "=r"(r[1]), "=r"(r[2]), "=r"(r[3]) : "r"(addr));
}
__device__ __forceinline__ void mma16816(float* c, const uint32_t* a, uint32_t b0, uint32_t b1) {
    asm volatile("mma.sync.aligned.m16n8k16.row.col.f32.bf16.bf16.f32 "
        "{%0,%1,%2,%3}, {%4,%5,%6,%7}, {%8,%9}, {%0,%1,%2,%3};"
        : "+f"(c[0]), "+f"(c[1]), "+f"(c[2]), "+f"(c[3])
        : "r"(a[0]), "r"(a[1]), "r"(a[2]), "r"(a[3]), "r"(b0), "r"(b1));
}
__device__ __forceinline__ uint32_t hl_pack(float v) {
    __nv_bfloat16 hi = __float2bfloat16(v);
    __nv_bfloat16 lo = __float2bfloat16(v - __bfloat162float(hi));
    return (uint32_t)__bfloat16_as_ushort(hi) | ((uint32_t)__bfloat16_as_ushort(lo) << 16);
}

// ===========================================================================
// prep: Whh transpose, bias sums, conv weight tiles
// ===========================================================================
__global__ void prep_kernel(const float* __restrict__ whh_f, const float* __restrict__ whh_b,
                            const float* __restrict__ bih_f, const float* __restrict__ bhh_f,
                            const float* __restrict__ bih_b, const float* __restrict__ bhh_b,
                            const float* __restrict__ c2w1, const float* __restrict__ c2w2,
                            const float* __restrict__ cvw1, const float* __restrict__ cvw2)
{
    unsigned i = blockIdx.x * 256u + threadIdx.x;
    if (i < 512u * 128u) {
        int g = i / 128, k = i % 128;
        g_whhT[0][k * 512 + g] = whh_f[i];
        g_whhT[1][k * 512 + g] = whh_b[i];
    }
    if (i < 512u) {
        g_bias2[0][i] = bih_f[i] + bhh_f[i];
        g_bias2[1][i] = bih_b[i] + bhh_b[i];
    }
    if (i < 11206656u) {
        unsigned l; int CC; int kind;
        if      (i < WB_B) { l = i - WB_A; CC = 8;  kind = 0; }
        else if (i < WB_C) { l = i - WB_B; CC = 8;  kind = 1; }
        else if (i < WB_E) { l = i - WB_C; CC = 16; kind = 2; }
        else if (i < WB_F) { l = i - WB_E; CC = 8;  kind = 3; }
        else               { l = i - WB_F; CC = 4;  kind = 4; }
        int n    = l & 127;
        int k    = (l >> 7) & 63;
        int pass = (l >> 13) & 1;
        unsigned q = l >> 14;
        int cc  = q % CC;  q /= CC;
        int tap = q % 9;   q /= 9;
        int ot  = q;
        int c  = cc * 32 + (k >> 1);
        int oc = ot * 128 + n;
        int odd = k & 1;
        float w;
        if      (kind == 0) w = c2w1[((size_t)oc * 512 + c) * 9 + tap]
                              + c2w1[((size_t)oc * 512 + c + 256) * 9 + tap];
        else if (kind == 1) w = c2w2[((size_t)oc * 256 + c) * 9 + tap];
        else if (kind == 2) w = c2w1[((size_t)oc * 512 + c) * 9 + tap];
        else if (kind == 3) w = cvw1[((size_t)oc * 256 + c) * 9 + tap];
        else                w = cvw2[((size_t)oc * 128 + c) * 9 + tap];
        __nv_bfloat16 hi = __float2bfloat16(w);
        __nv_bfloat16 val;
        if (pass == 0) val = hi;
        else val = odd ? __float2bfloat16(0.f)
                       : __float2bfloat16(w - __bfloat162float(hi));
        g_wb[i] = val;
    }
}

// xg-GEMM B fragments: [nt][cc][pass][k][n]; nt 0-3 = fwd gates, 4-7 = bwd
__global__ void prep2_kernel(const float* __restrict__ wih_f,
                             const float* __restrict__ wih_b)
{
    unsigned i = blockIdx.x * 256u + threadIdx.x;
    if (i >= 1048576u) return;
    int n    = i & 127;
    int k    = (i >> 7) & 63;
    int pass = (i >> 13) & 1;
    int cc   = (i >> 14) & 7;
    int nt   = (int)(i >> 17);
    int c    = cc * 32 + (k >> 1);
    int odd  = k & 1;
    const float* W = (nt >= 4) ? wih_b : wih_f;
    int gate = (nt & 3) * 128 + n;
    float w = W[gate * 256 + c];
    __nv_bfloat16 hi = __float2bfloat16(w);
    __nv_bfloat16 val;
    if (pass == 0) val = hi;
    else val = odd ? __float2bfloat16(0.f)
                   : __float2bfloat16(w - __bfloat162float(hi));
    g_wih_frag[i] = val;
}

// ===========================================================================
// build rows-sequence (upsample + concat) -> hl-packed NHWC
// ===========================================================================
__global__ __launch_bounds__(256) void build_seq_kernel(const float* __restrict__ x2,
                                                        const float* __restrict__ x1)
{
    __shared__ float sh[32][65];
    int bh = blockIdx.x;
    int b = bh >> 6, h = bh & 63;
    int ct = blockIdx.y;
    int c0 = ct * 32;
    int tid = threadIdx.x;

    if (ct < 4) {
        for (int idx = tid; idx < 32 * 64; idx += 256) {
            int ci = idx >> 6, w = idx & 63;
            sh[ci][w] = x2[(((size_t)b * 128 + (c0 + ci)) * 64 + h) * 64 + w];
        }
    } else {
        int cc0 = c0 - 128;
        float py = (float)h * 31.0f / 63.0f;
        int yl = (int)floorf(py);
        float wy = py - (float)yl;
        int yh = min(yl + 1, 31);
        for (int idx = tid; idx < 32 * 64; idx += 256) {
            int ci = idx >> 6, w = idx & 63;
            float px = (float)w * 31.0f / 63.0f;
            int xl = (int)floorf(px);
            float wx = px - (float)xl;
            int xh = min(xl + 1, 31);
            const float* base = x1 + ((size_t)b * 128 + (cc0 + ci)) * 1024;
            float v00 = base[yl * 32 + xl], v01 = base[yl * 32 + xh];
            float v10 = base[yh * 32 + xl], v11 = base[yh * 32 + xh];
            float v0 = v00 * (1.f - wx) + v01 * wx;
            float v1 = v10 * (1.f - wx) + v11 * wx;
            sh[ci][w] = v0 * (1.f - wy) + v1 * wy;
        }
    }
    __syncthreads();
    for (int idx = tid; idx < 32 * 64; idx += 256) {
        int w = idx >> 5, cl = idx & 31;
        g_seq[((size_t)bh * 64 + w) * 256 + c0 + cl] = hl_pack(sh[cl][w]);
    }
}

// ===========================================================================
// xg GEMM via mma: xg[32768,1024] = A_hl[32768,256ch] @ wih_frag + bias.
// CTA: 128 rows x 128 gates (blockIdx.y = nt). 256 threads = 8 warps (4Mx2N).
// ===========================================================================
#define GA_BYTES (128 * 144)
#define GB_BYTES (64 * 272)
#define G_SMEM   (GA_BYTES + 2 * GB_BYTES)

__global__ __launch_bounds__(256, 2) void gemm_mma_kernel(const uint32_t* __restrict__ Ahl)
{
    extern __shared__ __align__(16) char smem[];
    char* a_sh = smem;
    char* b_sh = smem + GA_BYTES;

    int tid = threadIdx.x;
    int lane = tid & 31, wid = tid >> 5;
    int warp_m = wid & 3, warp_n = wid >> 2;
    int mbase = blockIdx.x * 128;
    int nt = blockIdx.y;
    int dir = nt >> 2;
    int gbase = (nt & 3) * 128;

    float acc[2][8][4];
#pragma unroll
    for (int m = 0; m < 2; m++)
#pragma unroll
        for (int j = 0; j < 8; j++)
#pragma unroll
            for (int q = 0; q < 4; q++) acc[m][j][q] = 0.f;

    uint32_t a_base = smem_u32(a_sh);
    uint32_t b_base = smem_u32(b_sh);

    int arow = warp_m * 32 + (lane & 7) + ((lane >> 3) & 1) * 8;
    uint32_t a_addr0 = a_base + arow * 144 + ((lane >> 4) * 16);
    int brow = (lane & 7) + ((lane >> 3) & 1) * 8;
    int bcol = warp_n * 64 + ((lane >> 4) * 8);
    uint32_t b_addr0 = b_base + brow * 272 + bcol * 2;

    int s_px = tid >> 1, s_half = tid & 1;

    for (int cc = 0; cc < 8; cc++) {
        {
            const uint4* src = (const uint4*)(Ahl + ((size_t)(mbase + s_px)) * 256 + cc * 32 + s_half * 16);
            uint4* dst = (uint4*)(a_sh + s_px * 144 + s_half * 64);
#pragma unroll
            for (int i = 0; i < 4; i++) dst[i] = src[i];
        }
        const uint4* wsrc = (const uint4*)(g_wih_frag + ((size_t)(nt * 8 + cc)) * 16384u);
#pragma unroll
        for (int i = 0; i < 8; i++) {
            int idx = tid + i * 256;
            int pofs = (idx >= 1024) ? GB_BYTES : 0;
            int li = idx & 1023;
            *(uint4*)(b_sh + pofs + (li >> 4) * 272 + (li & 15) * 16) = wsrc[idx];
        }
        __syncthreads();
#pragma unroll
        for (int pass = 0; pass < 2; pass++) {
            uint32_t bp = b_addr0 + pass * GB_BYTES;
#pragma unroll
            for (int ksub = 0; ksub < 4; ksub++) {
                uint32_t a0[4], a1[4];
                ldsm4(a0, a_addr0 + ksub * 32);
                ldsm4(a1, a_addr0 + 16 * 144 + ksub * 32);
                uint32_t bfr[4][4];
#pragma unroll
                for (int p = 0; p < 4; p++)
                    ldsm4t(bfr[p], bp + ksub * 16 * 272 + p * 32);
#pragma unroll
                for (int j = 0; j < 8; j++) {
                    uint32_t bq0 = bfr[j >> 1][(j & 1) * 2];
                    uint32_t bq1 = bfr[j >> 1][(j & 1) * 2 + 1];
                    mma16816(acc[0][j], a0, bq0, bq1);
                    mma16816(acc[1][j], a1, bq0, bq1);
                }
            }
        }
        __syncthreads();
    }

#pragma unroll
    for (int m = 0; m < 2; m++) {
        int px0 = warp_m * 32 + m * 16 + (lane >> 2);
#pragma unroll
        for (int j = 0; j < 8; j++) {
            int oc = warp_n * 64 + j * 8 + (lane & 3) * 2;
            float b0 = g_bias2[dir][gbase + oc];
            float b1 = g_bias2[dir][gbase + oc + 1];
            size_t col = (size_t)dir * 512 + gbase + oc;
            float* r0 = &g_xg[(size_t)(mbase + px0) * 1024 + col];
            float* r1 = &g_xg[(size_t)(mbase + px0 + 8) * 1024 + col];
            *(float2*)r0 = make_float2(acc[m][j][0] + b0, acc[m][j][1] + b1);
            *(float2*)r1 = make_float2(acc[m][j][2] + b0, acc[m][j][3] + b1);
        }
    }
}

// ===========================================================================
// LSTM recurrence: R8 config (best measured: 256 blocks, 4 seqs/block).
// dir = blk>>7, thread = 2 seq x 4 gates; activation 2 cells/thread.
// BOTH modes store hl-packed uint32 with the same index formula.
// ===========================================================================
__global__ __launch_bounds__(256) void lstm_kernel(int mode)
{
    int dir = blockIdx.x >> 7;
    int blk = blockIdx.x & 127;
    const float* whhT = g_whhT[dir];
    const float* xg = g_xg + dir * 512;
    uint32_t* out = mode ? g_cols_hl : g_rows_hl;

    __shared__ __align__(16) float h_sh[4][132];
    __shared__ __align__(16) float g_sh[4][516];

    int tid = threadIdx.x;
    int ts = tid >> 7;           // 0..1
    int tg = tid & 127;
    int g0 = tg * 4;
    int sb = ts * 2;             // 2 sequences per thread
    int base_n = blk * 4;

    float c_reg[2] = {0.f, 0.f};

    for (int t = 0; t < 64; t++) {
        int ta = dir ? (63 - t) : t;
        float acc[2][4];
#pragma unroll
        for (int si = 0; si < 2; si++) {
            int n = base_n + sb + si;
            float4 v = *(const float4*)&xg[((size_t)n * 64 + ta) * 1024 + g0];
            acc[si][0] = v.x; acc[si][1] = v.y; acc[si][2] = v.z; acc[si][3] = v.w;
        }
        if (t > 0) {
#pragma unroll 4
            for (int k = 0; k < 128; k++) {
                float4 w = *(const float4*)&whhT[(k << 9) + g0];
                float h0 = h_sh[sb + 0][k];
                float h1 = h_sh[sb + 1][k];
                acc[0][0] += h0 * w.x; acc[0][1] += h0 * w.y;
                acc[0][2] += h0 * w.z; acc[0][3] += h0 * w.w;
                acc[1][0] += h1 * w.x; acc[1][1] += h1 * w.y;
                acc[1][2] += h1 * w.z; acc[1][3] += h1 * w.w;
            }
        }
#pragma unroll
        for (int si = 0; si < 2; si++) {
            *(float4*)&g_sh[sb + si][g0] =
                make_float4(acc[si][0], acc[si][1], acc[si][2], acc[si][3]);
        }
        __syncthreads();
#pragma unroll
        for (int p = 0; p < 2; p++) {
            int idx = tid + p * 256;
            int s = idx >> 7, j = idx & 127;
            float iv = g_sh[s][j];
            float fv = g_sh[s][128 + j];
            float gv = g_sh[s][256 + j];
            float ov = g_sh[s][384 + j];
            float ig = 1.f / (1.f + expf(-iv));
            float fg = 1.f / (1.f + expf(-fv));
            float og = 1.f / (1.f + expf(-ov));
            c_reg[p] = fg * c_reg[p] + ig * tanhf(gv);
            float h = og * tanhf(c_reg[p]);
            h_sh[s][j] = h;
            int n = base_n + s;
            int b = n >> 6, loc = n & 63;
            out[(((size_t)(b * 64 + ta)) * 64 + loc) * 256 + dir * 128 + j] = hl_pack(h);
        }
        __syncthreads();
    }
}

// ===========================================================================
// mma.sync bf16 implicit-GEMM 3x3 conv (R8 version — best measured).
// ===========================================================================
#define CONV_A_BYTES   (128 * 144)
#define CONV_B_BYTES   (64 * 272)
#define CONV_SMEM      (CONV_A_BYTES + 2 * CONV_B_BYTES)

__global__ __launch_bounds__(256, 2) void conv_mma_kernel(
    const uint32_t* __restrict__ in0, int C0,
    const uint32_t* __restrict__ in1, int C1,
    unsigned wb_off,
    const float* __restrict__ gamma, const float* __restrict__ beta,
    void* outp, int OC, int final_nchw)
{
    extern __shared__ __align__(16) char smem[];
    char* a_sh = smem;
    char* b_sh = smem + CONV_A_BYTES;
    __shared__ float scs[128], bbs[128];

    int tid = threadIdx.x;
    int lane = tid & 31, wid = tid >> 5;
    int warp_m = wid & 3, warp_n = wid >> 2;
    int bx = blockIdx.x;
    int b = bx >> 5, y0 = (bx & 31) * 2;
    int ot = blockIdx.y, ocb = ot * 128;
    int CIN = C0 + C1, CC = CIN >> 5;

    if (tid < 128) {
        scs[tid] = gamma[ocb + tid] * rsqrtf(1.f + EPS_BN);
        bbs[tid] = beta[ocb + tid];
    }

    float acc[2][8][4];
#pragma unroll
    for (int m = 0; m < 2; m++)
#pragma unroll
        for (int j = 0; j < 8; j++)
#pragma unroll
            for (int q = 0; q < 4; q++) acc[m][j][q] = 0.f;

    uint32_t a_base = smem_u32(a_sh);
    uint32_t b_base = smem_u32(b_sh);

    int arow = warp_m * 32 + (lane & 7) + ((lane >> 3) & 1) * 8;
    uint32_t a_addr0 = a_base + arow * 144 + ((lane >> 4) * 16);
    int brow = (lane & 7) + ((lane >> 3) & 1) * 8;
    int bcol = warp_n * 64 + ((lane >> 4) * 8);
    uint32_t b_addr0 = b_base + brow * 272 + bcol * 2;

    int s_px = tid >> 1, s_half = tid & 1;
    int s_yo = s_px >> 6, s_x = s_px & 63;

    for (int tap = 0; tap < 9; tap++) {
        int ty = tap / 3 - 1, tx = tap % 3 - 1;
        int ys = y0 + s_yo + ty;
        int xs = s_x + tx;
        bool ok = ((unsigned)ys < 64u) && ((unsigned)xs < 64u);
        for (int cc = 0; cc < CC; cc++) {
            {
                int c0 = cc * 32 + s_half * 16;
                const uint4* src;
                if (c0 < C0) src = (const uint4*)(in0 + ((size_t)((b * 64 + ys) * 64 + xs)) * C0 + c0);
                else         src = (const uint4*)(in1 + ((size_t)((b * 64 + ys) * 64 + xs)) * C1 + (c0 - C0));
                uint4* dst = (uint4*)(a_sh + s_px * 144 + s_half * 64);
#pragma unroll
                for (int i = 0; i < 4; i++) {
                    uint4 v = make_uint4(0u, 0u, 0u, 0u);
                    if (ok) v = src[i];
                    dst[i] = v;
                }
            }
            const uint4* wsrc = (const uint4*)(g_wb + wb_off +
                ((size_t)((ot * 9 + tap) * CC + cc)) * 16384u);
#pragma unroll
            for (int i = 0; i < 8; i++) {
                int idx = tid + i * 256;
                int pofs = (idx >= 1024) ? CONV_B_BYTES : 0;
                int li = idx & 1023;
                *(uint4*)(b_sh + pofs + (li >> 4) * 272 + (li & 15) * 16) = wsrc[idx];
            }
            __syncthreads();
#pragma unroll
            for (int pass = 0; pass < 2; pass++) {
                uint32_t bp = b_addr0 + pass * CONV_B_BYTES;
#pragma unroll
                for (int ksub = 0; ksub < 4; ksub++) {
                    uint32_t a0[4], a1[4];
                    ldsm4(a0, a_addr0 + ksub * 32);
                    ldsm4(a1, a_addr0 + 16 * 144 + ksub * 32);
                    uint32_t bfr[4][4];
#pragma unroll
                    for (int p = 0; p < 4; p++)
                        ldsm4t(bfr[p], bp + ksub * 16 * 272 + p * 32);
#pragma unroll
                    for (int j = 0; j < 8; j++) {
                        uint32_t bq0 = bfr[j >> 1][(j & 1) * 2];
                        uint32_t bq1 = bfr[j >> 1][(j & 1) * 2 + 1];
                        mma16816(acc[0][j], a0, bq0, bq1);
                        mma16816(acc[1][j], a1, bq0, bq1);
                    }
                }
            }
            __syncthreads();
        }
    }

#pragma unroll
    for (int m = 0; m < 2; m++) {
        int px0 = warp_m * 32 + m * 16 + (lane >> 2);
#pragma unroll
        for (int j = 0; j < 8; j++) {
            int oc = warp_n * 64 + j * 8 + (lane & 3) * 2;
            float sc0 = scs[oc], sc1 = scs[oc + 1];
            float bb0 = bbs[oc], bb1 = bbs[oc + 1];
            float v00 = fmaxf(fmaf(acc[m][j][0], sc0, bb0), 0.f);
            float v01 = fmaxf(fmaf(acc[m][j][1], sc1, bb1), 0.f);
            float v10 = fmaxf(fmaf(acc[m][j][2], sc0, bb0), 0.f);
            float v11 = fmaxf(fmaf(acc[m][j][3], sc1, bb1), 0.f);
            if (!final_nchw) {
                uint32_t* out = (uint32_t*)outp;
                size_t base0 = ((size_t)((b * 64 + (y0 + (px0 >> 6))) * 64 + (px0 & 63))) * OC + ocb + oc;
                int px1 = px0 + 8;
                size_t base1 = ((size_t)((b * 64 + (y0 + (px1 >> 6))) * 64 + (px1 & 63))) * OC + ocb + oc;
                *(uint2*)(out + base0) = make_uint2(hl_pack(v00), hl_pack(v01));
                *(uint2*)(out + base1) = make_uint2(hl_pack(v10), hl_pack(v11));
            } else {
                float* out = (float*)outp;
                size_t r0 = ((size_t)b * OC + ocb + oc) * 4096 + y0 * 64;
                size_t r1 = ((size_t)b * OC + ocb + oc + 1) * 4096 + y0 * 64;
                out[r0 + px0] = v00;
                out[r1 + px0] = v01;
                out[r0 + px0 + 8] = v10;
                out[r1 + px0 + 8] = v11;
            }
        }
    }
}

// ===========================================================================
// launcher
// ===========================================================================
extern "C" void kernel_launch(void* const* d_in, const int* in_sizes, int n_in,
                              void* d_out, int out_size)
{
    const float* x1    = (const float*)d_in[0];
    const float* x2    = (const float*)d_in[1];
    const float* wih_f = (const float*)d_in[2];
    const float* whh_f = (const float*)d_in[3];
    const float* bih_f = (const float*)d_in[4];
    const float* bhh_f = (const float*)d_in[5];
    const float* wih_b = (const float*)d_in[6];
    const float* whh_b = (const float*)d_in[7];
    const float* bih_b = (const float*)d_in[8];
    const float* bhh_b = (const float*)d_in[9];
    const float* c2_w1 = (const float*)d_in[10];
    const float* c2_g1 = (const float*)d_in[11];
    const float* c2_b1 = (const float*)d_in[12];
    const float* c2_w2 = (const float*)d_in[13];
    const float* c2_g2 = (const float*)d_in[14];
    const float* c2_b2 = (const float*)d_in[15];
    const float* cv_w1 = (const float*)d_in[16];
    const float* cv_g1 = (const float*)d_in[17];
    const float* cv_b1 = (const float*)d_in[18];
    const float* cv_w2 = (const float*)d_in[19];
    const float* cv_g2 = (const float*)d_in[20];
    const float* cv_b2 = (const float*)d_in[21];

    uint32_t *p_seq = nullptr, *p_rows_hl = nullptr, *p_cols = nullptr,
             *p_hlB = nullptr, *p_hlC = nullptr, *p_hlD = nullptr;
    cudaGetSymbolAddress((void**)&p_seq, g_seq);
    cudaGetSymbolAddress((void**)&p_rows_hl, g_rows_hl);
    cudaGetSymbolAddress((void**)&p_cols, g_cols_hl);
    cudaGetSymbolAddress((void**)&p_hlB, g_hlB);
    cudaGetSymbolAddress((void**)&p_hlC, g_hlC);
    cudaGetSymbolAddress((void**)&p_hlD, g_hlD);

    cudaFuncSetAttribute(conv_mma_kernel,
                         cudaFuncAttributeMaxDynamicSharedMemorySize, CONV_SMEM);
    cudaFuncSetAttribute(gemm_mma_kernel,
                         cudaFuncAttributeMaxDynamicSharedMemorySize, G_SMEM);

    prep_kernel<<<43776, 256>>>(whh_f, whh_b, bih_f, bhh_f, bih_b, bhh_b,
                                c2_w1, c2_w2, cv_w1, cv_w2);
    prep2_kernel<<<4096, 256>>>(wih_f, wih_b);
    build_seq_kernel<<<dim3(512, 8), 256>>>(x2, x1);

    // rows pass
    gemm_mma_kernel<<<dim3(256, 8), 256, G_SMEM>>>(p_seq);
    lstm_kernel<<<256, 256>>>(0);

    // cols pass
    gemm_mma_kernel<<<dim3(256, 8), 256, G_SMEM>>>(p_rows_hl);
    lstm_kernel<<<256, 256>>>(1);

    // x_site = double_conv(concat([x,x])) via folded weights (A), then c2_w2 (B)
    conv_mma_kernel<<<dim3(256, 2), 256, CONV_SMEM>>>(p_cols, 256, nullptr, 0, WB_A,
                                                      c2_g1, c2_b1, p_hlB, 256, 0);
    conv_mma_kernel<<<dim3(256, 2), 256, CONV_SMEM>>>(p_hlB, 256, nullptr, 0, WB_B,
                                                      c2_g2, c2_b2, p_hlC, 256, 0);
    // x = double_conv(concat([x, x_site]))
    conv_mma_kernel<<<dim3(256, 2), 256, CONV_SMEM>>>(p_cols, 256, p_hlC, 256, WB_C,
                                                      c2_g1, c2_b1, p_hlB, 256, 0);
    conv_mma_kernel<<<dim3(256, 2), 256, CONV_SMEM>>>(p_hlB, 256, nullptr, 0, WB_B,
                                                      c2_g2, c2_b2, p_hlC, 256, 0);
    // final double_conv (cv): 256->128, 128->128 -> d_out (fp32 NCHW)
    conv_mma_kernel<<<dim3(256, 1), 256, CONV_SMEM>>>(p_hlC, 256, nullptr, 0, WB_E,
                                                      cv_g1, cv_b1, p_hlD, 128, 0);
    conv_mma_kernel<<<dim3(256, 1), 256, CONV_SMEM>>>(p_hlD, 128, nullptr, 0, WB_F,
                                                      cv_g2, cv_b2, d_out, 128, 1);
}

// round 14
// speedup vs baseline: 1.1869x; 1.0104x over previous
#include <cuda_runtime.h>
#include <cuda_bf16.h>
#include <cstdint>
#include <math.h>

#define EPS_BN 1e-5f

// ===========================================================================
// scratch (device globals)
// ===========================================================================
__device__ uint32_t g_seq [8388608];      // rows-seq hl NHWC
__device__ float    g_xg  [33554432];     // 32768 x 1024 (gate-permuted per dir)
__device__ uint32_t g_rows_hl[8388608];   // rows-LSTM out hl [b][w][h][c]
__device__ uint32_t g_cols_hl[8388608];   // cols-LSTM out NHWC hl
__device__ uint32_t g_hlB[8388608];       // conv temps, NHWC hl
__device__ uint32_t g_hlC[8388608];
__device__ uint32_t g_hlD[4194304];       // 128-channel temp
__device__ __nv_bfloat16 g_wb[11206656];  // conv weights: [ot][tap][cc][pass][k64][n128]
__device__ __nv_bfloat16 g_wih_frag[1048576]; // xg-GEMM B (permuted gates)
__device__ float    g_whhT[2][65536];     // [dir][k][permuted gate]
__device__ float    g_bias2[2][512];      // permuted

// wb region offsets (elements)
#define WB_A 0u
#define WB_B 2359296u
#define WB_C 4718592u
#define WB_E 9437184u
#define WB_F 10616832u

// ===========================================================================
// mma.sync / ldmatrix helpers
// ===========================================================================
__device__ __forceinline__ uint32_t smem_u32(const void* p) {
    uint32_t a;
    asm("{ .reg .u64 t; cvta.to.shared.u64 t, %1; cvt.u32.u64 %0, t; }" : "=r"(a) : "l"(p));
    return a;
}
__device__ __forceinline__ void ldsm4(uint32_t* r, uint32_t addr) {
    asm volatile("ldmatrix.sync.aligned.m8n8.x4.shared.b16 {%0,%1,%2,%3}, [%4];"
        : "=r"(r[0]), "=r"(r[1]), "=r"(r[2]), "=r"(r[3]) : "r"(addr));
}
__device__ __forceinline__ void ldsm4t(uint32_t* r, uint32_t addr) {
    asm volatile("ldmatrix.sync.aligned.m8n8.x4.trans.shared.b16 {%0,%1,%2,%3}, [%4];"
        : "=r"(r[0]), "=r"(r[1]), "=r"(r[2]), "=r"(r[3]) : "r"(addr));
}
__device__ __forceinline__ void mma16816(float* c, const uint32_t* a, uint32_t b0, uint32_t b1) {
    asm volatile("mma.sync.aligned.m16n8k16.row.col.f32.bf16.bf16.f32 "
        "{%0,%1,%2,%3}, {%4,%5,%6,%7}, {%8,%9}, {%0,%1,%2,%3};"
        : "+f"(c[0]), "+f"(c[1]), "+f"(c[2]), "+f"(c[3])
        : "r"(a[0]), "r"(a[1]), "r"(a[2]), "r"(a[3]), "r"(b0), "r"(b1));
}
__device__ __forceinline__ uint32_t hl_pack(float v) {
    __nv_bfloat16 hi = __float2bfloat16(v);
    __nv_bfloat16 lo = __float2bfloat16(v - __bfloat162float(hi));
    return (uint32_t)__bfloat16_as_ushort(hi) | ((uint32_t)__bfloat16_as_ushort(lo) << 16);
}

// ===========================================================================
// prep: Whh transpose (gate-permuted), bias sums (permuted), conv weight tiles
// permutation: orig gate g = q*128 + cell  ->  pg = cell*4 + q
// ===========================================================================
__global__ void prep_kernel(const float* __restrict__ whh_f, const float* __restrict__ whh_b,
                            const float* __restrict__ bih_f, const float* __restrict__ bhh_f,
                            const float* __restrict__ bih_b, const float* __restrict__ bhh_b,
                            const float* __restrict__ c2w1, const float* __restrict__ c2w2,
                            const float* __restrict__ cvw1, const float* __restrict__ cvw2)
{
    unsigned i = blockIdx.x * 256u + threadIdx.x;
    if (i < 512u * 128u) {
        int g = i / 128, k = i % 128;
        int pg = (g & 127) * 4 + (g >> 7);
        g_whhT[0][k * 512 + pg] = whh_f[i];
        g_whhT[1][k * 512 + pg] = whh_b[i];
    }
    if (i < 512u) {
        int pg = (i & 127) * 4 + (i >> 7);
        g_bias2[0][pg] = bih_f[i] + bhh_f[i];
        g_bias2[1][pg] = bih_b[i] + bhh_b[i];
    }
    if (i < 11206656u) {
        unsigned l; int CC; int kind;
        if      (i < WB_B) { l = i - WB_A; CC = 8;  kind = 0; }
        else if (i < WB_C) { l = i - WB_B; CC = 8;  kind = 1; }
        else if (i < WB_E) { l = i - WB_C; CC = 16; kind = 2; }
        else if (i < WB_F) { l = i - WB_E; CC = 8;  kind = 3; }
        else               { l = i - WB_F; CC = 4;  kind = 4; }
        int n    = l & 127;
        int k    = (l >> 7) & 63;
        int pass = (l >> 13) & 1;
        unsigned q = l >> 14;
        int cc  = q % CC;  q /= CC;
        int tap = q % 9;   q /= 9;
        int ot  = q;
        int c  = cc * 32 + (k >> 1);
        int oc = ot * 128 + n;
        int odd = k & 1;
        float w;
        if      (kind == 0) w = c2w1[((size_t)oc * 512 + c) * 9 + tap]
                              + c2w1[((size_t)oc * 512 + c + 256) * 9 + tap];
        else if (kind == 1) w = c2w2[((size_t)oc * 256 + c) * 9 + tap];
        else if (kind == 2) w = c2w1[((size_t)oc * 512 + c) * 9 + tap];
        else if (kind == 3) w = cvw1[((size_t)oc * 256 + c) * 9 + tap];
        else                w = cvw2[((size_t)oc * 128 + c) * 9 + tap];
        __nv_bfloat16 hi = __float2bfloat16(w);
        __nv_bfloat16 val;
        if (pass == 0) val = hi;
        else val = odd ? __float2bfloat16(0.f)
                       : __float2bfloat16(w - __bfloat162float(hi));
        g_wb[i] = val;
    }
}

// xg-GEMM B fragments with PERMUTED gate columns:
// permuted gate pg = (nt&3)*128 + n; cell = pg>>2; q = pg&3; orig = q*128+cell
__global__ void prep2_kernel(const float* __restrict__ wih_f,
                             const float* __restrict__ wih_b)
{
    unsigned i = blockIdx.x * 256u + threadIdx.x;
    if (i >= 1048576u) return;
    int n    = i & 127;
    int k    = (i >> 7) & 63;
    int pass = (i >> 13) & 1;
    int cc   = (i >> 14) & 7;
    int nt   = (int)(i >> 17);
    int c    = cc * 32 + (k >> 1);
    int odd  = k & 1;
    const float* W = (nt >= 4) ? wih_b : wih_f;
    int pg   = (nt & 3) * 128 + n;
    int gate = (pg & 3) * 128 + (pg >> 2);
    float w = W[gate * 256 + c];
    __nv_bfloat16 hi = __float2bfloat16(w);
    __nv_bfloat16 val;
    if (pass == 0) val = hi;
    else val = odd ? __float2bfloat16(0.f)
                   : __float2bfloat16(w - __bfloat162float(hi));
    g_wih_frag[i] = val;
}

// ===========================================================================
// build rows-sequence (upsample + concat) -> hl-packed NHWC
// ===========================================================================
__global__ __launch_bounds__(256) void build_seq_kernel(const float* __restrict__ x2,
                                                        const float* __restrict__ x1)
{
    __shared__ float sh[32][65];
    int bh = blockIdx.x;
    int b = bh >> 6, h = bh & 63;
    int ct = blockIdx.y;
    int c0 = ct * 32;
    int tid = threadIdx.x;

    if (ct < 4) {
        for (int idx = tid; idx < 32 * 64; idx += 256) {
            int ci = idx >> 6, w = idx & 63;
            sh[ci][w] = x2[(((size_t)b * 128 + (c0 + ci)) * 64 + h) * 64 + w];
        }
    } else {
        int cc0 = c0 - 128;
        float py = (float)h * 31.0f / 63.0f;
        int yl = (int)floorf(py);
        float wy = py - (float)yl;
        int yh = min(yl + 1, 31);
        for (int idx = tid; idx < 32 * 64; idx += 256) {
            int ci = idx >> 6, w = idx & 63;
            float px = (float)w * 31.0f / 63.0f;
            int xl = (int)floorf(px);
            float wx = px - (float)xl;
            int xh = min(xl + 1, 31);
            const float* base = x1 + ((size_t)b * 128 + (cc0 + ci)) * 1024;
            float v00 = base[yl * 32 + xl], v01 = base[yl * 32 + xh];
            float v10 = base[yh * 32 + xl], v11 = base[yh * 32 + xh];
            float v0 = v00 * (1.f - wx) + v01 * wx;
            float v1 = v10 * (1.f - wx) + v11 * wx;
            sh[ci][w] = v0 * (1.f - wy) + v1 * wy;
        }
    }
    __syncthreads();
    for (int idx = tid; idx < 32 * 64; idx += 256) {
        int w = idx >> 5, cl = idx & 31;
        g_seq[((size_t)bh * 64 + w) * 256 + c0 + cl] = hl_pack(sh[cl][w]);
    }
}

// ===========================================================================
// xg GEMM via mma (A-fragment hoisted across hi/lo passes).
// ===========================================================================
#define GA_BYTES (128 * 144)
#define GB_BYTES (64 * 272)
#define G_SMEM   (GA_BYTES + 2 * GB_BYTES)

__global__ __launch_bounds__(256, 2) void gemm_mma_kernel(const uint32_t* __restrict__ Ahl)
{
    extern __shared__ __align__(16) char smem[];
    char* a_sh = smem;
    char* b_sh = smem + GA_BYTES;

    int tid = threadIdx.x;
    int lane = tid & 31, wid = tid >> 5;
    int warp_m = wid & 3, warp_n = wid >> 2;
    int mbase = blockIdx.x * 128;
    int nt = blockIdx.y;
    int dir = nt >> 2;
    int gbase = (nt & 3) * 128;

    float acc[2][8][4];
#pragma unroll
    for (int m = 0; m < 2; m++)
#pragma unroll
        for (int j = 0; j < 8; j++)
#pragma unroll
            for (int q = 0; q < 4; q++) acc[m][j][q] = 0.f;

    uint32_t a_base = smem_u32(a_sh);
    uint32_t b_base = smem_u32(b_sh);

    int arow = warp_m * 32 + (lane & 7) + ((lane >> 3) & 1) * 8;
    uint32_t a_addr0 = a_base + arow * 144 + ((lane >> 4) * 16);
    int brow = (lane & 7) + ((lane >> 3) & 1) * 8;
    int bcol = warp_n * 64 + ((lane >> 4) * 8);
    uint32_t b_addr0 = b_base + brow * 272 + bcol * 2;

    int s_px = tid >> 1, s_half = tid & 1;

    for (int cc = 0; cc < 8; cc++) {
        {
            const uint4* src = (const uint4*)(Ahl + ((size_t)(mbase + s_px)) * 256 + cc * 32 + s_half * 16);
            uint4* dst = (uint4*)(a_sh + s_px * 144 + s_half * 64);
#pragma unroll
            for (int i = 0; i < 4; i++) dst[i] = src[i];
        }
        const uint4* wsrc = (const uint4*)(g_wih_frag + ((size_t)(nt * 8 + cc)) * 16384u);
#pragma unroll
        for (int i = 0; i < 8; i++) {
            int idx = tid + i * 256;
            int pofs = (idx >= 1024) ? GB_BYTES : 0;
            int li = idx & 1023;
            *(uint4*)(b_sh + pofs + (li >> 4) * 272 + (li & 15) * 16) = wsrc[idx];
        }
        __syncthreads();
#pragma unroll
        for (int ksub = 0; ksub < 4; ksub++) {
            uint32_t a0[4], a1[4];
            ldsm4(a0, a_addr0 + ksub * 32);
            ldsm4(a1, a_addr0 + 16 * 144 + ksub * 32);
#pragma unroll
            for (int pass = 0; pass < 2; pass++) {
                uint32_t bp = b_addr0 + pass * GB_BYTES;
                uint32_t bfr[4][4];
#pragma unroll
                for (int p = 0; p < 4; p++)
                    ldsm4t(bfr[p], bp + ksub * 16 * 272 + p * 32);
#pragma unroll
                for (int j = 0; j < 8; j++) {
                    uint32_t bq0 = bfr[j >> 1][(j & 1) * 2];
                    uint32_t bq1 = bfr[j >> 1][(j & 1) * 2 + 1];
                    mma16816(acc[0][j], a0, bq0, bq1);
                    mma16816(acc[1][j], a1, bq0, bq1);
                }
            }
        }
        __syncthreads();
    }

#pragma unroll
    for (int m = 0; m < 2; m++) {
        int px0 = warp_m * 32 + m * 16 + (lane >> 2);
#pragma unroll
        for (int j = 0; j < 8; j++) {
            int oc = warp_n * 64 + j * 8 + (lane & 3) * 2;
            float b0 = g_bias2[dir][gbase + oc];
            float b1 = g_bias2[dir][gbase + oc + 1];
            size_t col = (size_t)dir * 512 + gbase + oc;
            float* r0 = &g_xg[(size_t)(mbase + px0) * 1024 + col];
            float* r1 = &g_xg[(size_t)(mbase + px0 + 8) * 1024 + col];
            *(float2*)r0 = make_float2(acc[m][j][0] + b0, acc[m][j][1] + b1);
            *(float2*)r1 = make_float2(acc[m][j][2] + b0, acc[m][j][3] + b1);
        }
    }
}

// ===========================================================================
// LSTM recurrence, gate-permuted: thread = 1 cell x 2 seqs, activation
// entirely in registers; ONE barrier per step; h_sh double-buffered.
// 256 blocks (dir = blk>>7), 4 seqs/block, 256 threads.
// ===========================================================================
__global__ __launch_bounds__(256) void lstm_kernel(int mode)
{
    int dir = blockIdx.x >> 7;
    int blk = blockIdx.x & 127;
    const float* whhT = g_whhT[dir];
    const float* xg = g_xg + dir * 512;
    uint32_t* out = mode ? g_cols_hl : g_rows_hl;

    __shared__ __align__(16) float h_sh[2][4][132];

    int tid = threadIdx.x;
    int ts = tid >> 7;           // 0..1
    int tg = tid & 127;          // cell index
    int g0 = tg * 4;
    int sb = ts * 2;             // 2 sequences per thread
    int base_n = blk * 4;

    float c_reg[2] = {0.f, 0.f};

    for (int t = 0; t < 64; t++) {
        int ta = dir ? (63 - t) : t;
        int cur = t & 1, nxt = 1 - cur;
        float acc[2][4];
#pragma unroll
        for (int si = 0; si < 2; si++) {
            int n = base_n + sb + si;
            float4 v = *(const float4*)&xg[((size_t)n * 64 + ta) * 1024 + g0];
            acc[si][0] = v.x; acc[si][1] = v.y; acc[si][2] = v.z; acc[si][3] = v.w;
        }
        if (t > 0) {
#pragma unroll 4
            for (int k = 0; k < 128; k++) {
                float4 w = *(const float4*)&whhT[(k << 9) + g0];
                float h0 = h_sh[cur][sb + 0][k];
                float h1 = h_sh[cur][sb + 1][k];
                acc[0][0] += h0 * w.x; acc[0][1] += h0 * w.y;
                acc[0][2] += h0 * w.z; acc[0][3] += h0 * w.w;
                acc[1][0] += h1 * w.x; acc[1][1] += h1 * w.y;
                acc[1][2] += h1 * w.z; acc[1][3] += h1 * w.w;
            }
        }
#pragma unroll
        for (int si = 0; si < 2; si++) {
            float ig = 1.f / (1.f + expf(-acc[si][0]));
            float fg = 1.f / (1.f + expf(-acc[si][1]));
            float gv = tanhf(acc[si][2]);
            float og = 1.f / (1.f + expf(-acc[si][3]));
            c_reg[si] = fg * c_reg[si] + ig * gv;
            float h = og * tanhf(c_reg[si]);
            h_sh[nxt][sb + si][tg] = h;
            int n = base_n + sb + si;
            int b = n >> 6, loc = n & 63;
            out[(((size_t)(b * 64 + ta)) * 64 + loc) * 256 + dir * 128 + tg] = hl_pack(h);
        }
        __syncthreads();
    }
}

// ===========================================================================
// mma.sync bf16 implicit-GEMM 3x3 conv (R8 + A-fragment hoist).
// ===========================================================================
#define CONV_A_BYTES   (128 * 144)
#define CONV_B_BYTES   (64 * 272)
#define CONV_SMEM      (CONV_A_BYTES + 2 * CONV_B_BYTES)

__global__ __launch_bounds__(256, 2) void conv_mma_kernel(
    const uint32_t* __restrict__ in0, int C0,
    const uint32_t* __restrict__ in1, int C1,
    unsigned wb_off,
    const float* __restrict__ gamma, const float* __restrict__ beta,
    void* outp, int OC, int final_nchw)
{
    extern __shared__ __align__(16) char smem[];
    char* a_sh = smem;
    char* b_sh = smem + CONV_A_BYTES;
    __shared__ float scs[128], bbs[128];

    int tid = threadIdx.x;
    int lane = tid & 31, wid = tid >> 5;
    int warp_m = wid & 3, warp_n = wid >> 2;
    int bx = blockIdx.x;
    int b = bx >> 5, y0 = (bx & 31) * 2;
    int ot = blockIdx.y, ocb = ot * 128;
    int CIN = C0 + C1, CC = CIN >> 5;

    if (tid < 128) {
        scs[tid] = gamma[ocb + tid] * rsqrtf(1.f + EPS_BN);
        bbs[tid] = beta[ocb + tid];
    }

    float acc[2][8][4];
#pragma unroll
    for (int m = 0; m < 2; m++)
#pragma unroll
        for (int j = 0; j < 8; j++)
#pragma unroll
            for (int q = 0; q < 4; q++) acc[m][j][q] = 0.f;

    uint32_t a_base = smem_u32(a_sh);
    uint32_t b_base = smem_u32(b_sh);

    int arow = warp_m * 32 + (lane & 7) + ((lane >> 3) & 1) * 8;
    uint32_t a_addr0 = a_base + arow * 144 + ((lane >> 4) * 16);
    int brow = (lane & 7) + ((lane >> 3) & 1) * 8;
    int bcol = warp_n * 64 + ((lane >> 4) * 8);
    uint32_t b_addr0 = b_base + brow * 272 + bcol * 2;

    int s_px = tid >> 1, s_half = tid & 1;
    int s_yo = s_px >> 6, s_x = s_px & 63;

    for (int tap = 0; tap < 9; tap++) {
        int ty = tap / 3 - 1, tx = tap % 3 - 1;
        int ys = y0 + s_yo + ty;
        int xs = s_x + tx;
        bool ok = ((unsigned)ys < 64u) && ((unsigned)xs < 64u);
        for (int cc = 0; cc < CC; cc++) {
            {
                int c0 = cc * 32 + s_half * 16;
                const uint4* src;
                if (c0 < C0) src = (const uint4*)(in0 + ((size_t)((b * 64 + ys) * 64 + xs)) * C0 + c0);
                else         src = (const uint4*)(in1 + ((size_t)((b * 64 + ys) * 64 + xs)) * C1 + (c0 - C0));
                uint4* dst = (uint4*)(a_sh + s_px * 144 + s_half * 64);
#pragma unroll
                for (int i = 0; i < 4; i++) {
                    uint4 v = make_uint4(0u, 0u, 0u, 0u);
                    if (ok) v = src[i];
                    dst[i] = v;
                }
            }
            const uint4* wsrc = (const uint4*)(g_wb + wb_off +
                ((size_t)((ot * 9 + tap) * CC + cc)) * 16384u);
#pragma unroll
            for (int i = 0; i < 8; i++) {
                int idx = tid + i * 256;
                int pofs = (idx >= 1024) ? CONV_B_BYTES : 0;
                int li = idx & 1023;
                *(uint4*)(b_sh + pofs + (li >> 4) * 272 + (li & 15) * 16) = wsrc[idx];
            }
            __syncthreads();
#pragma unroll
            for (int ksub = 0; ksub < 4; ksub++) {
                uint32_t a0[4], a1[4];
                ldsm4(a0, a_addr0 + ksub * 32);
                ldsm4(a1, a_addr0 + 16 * 144 + ksub * 32);
#pragma unroll
                for (int pass = 0; pass < 2; pass++) {
                    uint32_t bp = b_addr0 + pass * CONV_B_BYTES;
                    uint32_t bfr[4][4];
#pragma unroll
                    for (int p = 0; p < 4; p++)
                        ldsm4t(bfr[p], bp + ksub * 16 * 272 + p * 32);
#pragma unroll
                    for (int j = 0; j < 8; j++) {
                        uint32_t bq0 = bfr[j >> 1][(j & 1) * 2];
                        uint32_t bq1 = bfr[j >> 1][(j & 1) * 2 + 1];
                        mma16816(acc[0][j], a0, bq0, bq1);
                        mma16816(acc[1][j], a1, bq0, bq1);
                    }
                }
            }
            __syncthreads();
        }
    }

#pragma unroll
    for (int m = 0; m < 2; m++) {
        int px0 = warp_m * 32 + m * 16 + (lane >> 2);
#pragma unroll
        for (int j = 0; j < 8; j++) {
            int oc = warp_n * 64 + j * 8 + (lane & 3) * 2;
            float sc0 = scs[oc], sc1 = scs[oc + 1];
            float bb0 = bbs[oc], bb1 = bbs[oc + 1];
            float v00 = fmaxf(fmaf(acc[m][j][0], sc0, bb0), 0.f);
            float v01 = fmaxf(fmaf(acc[m][j][1], sc1, bb1), 0.f);
            float v10 = fmaxf(fmaf(acc[m][j][2], sc0, bb0), 0.f);
            float v11 = fmaxf(fmaf(acc[m][j][3], sc1, bb1), 0.f);
            if (!final_nchw) {
                uint32_t* out = (uint32_t*)outp;
                size_t base0 = ((size_t)((b * 64 + (y0 + (px0 >> 6))) * 64 + (px0 & 63))) * OC + ocb + oc;
                int px1 = px0 + 8;
                size_t base1 = ((size_t)((b * 64 + (y0 + (px1 >> 6))) * 64 + (px1 & 63))) * OC + ocb + oc;
                *(uint2*)(out + base0) = make_uint2(hl_pack(v00), hl_pack(v01));
                *(uint2*)(out + base1) = make_uint2(hl_pack(v10), hl_pack(v11));
            } else {
                float* out = (float*)outp;
                size_t r0 = ((size_t)b * OC + ocb + oc) * 4096 + y0 * 64;
                size_t r1 = ((size_t)b * OC + ocb + oc + 1) * 4096 + y0 * 64;
                out[r0 + px0] = v00;
                out[r1 + px0] = v01;
                out[r0 + px0 + 8] = v10;
                out[r1 + px0 + 8] = v11;
            }
        }
    }
}

// ===========================================================================
// launcher
// ===========================================================================
extern "C" void kernel_launch(void* const* d_in, const int* in_sizes, int n_in,
                              void* d_out, int out_size)
{
    const float* x1    = (const float*)d_in[0];
    const float* x2    = (const float*)d_in[1];
    const float* wih_f = (const float*)d_in[2];
    const float* whh_f = (const float*)d_in[3];
    const float* bih_f = (const float*)d_in[4];
    const float* bhh_f = (const float*)d_in[5];
    const float* wih_b = (const float*)d_in[6];
    const float* whh_b = (const float*)d_in[7];
    const float* bih_b = (const float*)d_in[8];
    const float* bhh_b = (const float*)d_in[9];
    const float* c2_w1 = (const float*)d_in[10];
    const float* c2_g1 = (const float*)d_in[11];
    const float* c2_b1 = (const float*)d_in[12];
    const float* c2_w2 = (const float*)d_in[13];
    const float* c2_g2 = (const float*)d_in[14];
    const float* c2_b2 = (const float*)d_in[15];
    const float* cv_w1 = (const float*)d_in[16];
    const float* cv_g1 = (const float*)d_in[17];
    const float* cv_b1 = (const float*)d_in[18];
    const float* cv_w2 = (const float*)d_in[19];
    const float* cv_g2 = (const float*)d_in[20];
    const float* cv_b2 = (const float*)d_in[21];

    uint32_t *p_seq = nullptr, *p_rows_hl = nullptr, *p_cols = nullptr,
             *p_hlB = nullptr, *p_hlC = nullptr, *p_hlD = nullptr;
    cudaGetSymbolAddress((void**)&p_seq, g_seq);
    cudaGetSymbolAddress((void**)&p_rows_hl, g_rows_hl);
    cudaGetSymbolAddress((void**)&p_cols, g_cols_hl);
    cudaGetSymbolAddress((void**)&p_hlB, g_hlB);
    cudaGetSymbolAddress((void**)&p_hlC, g_hlC);
    cudaGetSymbolAddress((void**)&p_hlD, g_hlD);

    cudaFuncSetAttribute(conv_mma_kernel,
                         cudaFuncAttributeMaxDynamicSharedMemorySize, CONV_SMEM);
    cudaFuncSetAttribute(gemm_mma_kernel,
                         cudaFuncAttributeMaxDynamicSharedMemorySize, G_SMEM);

    prep_kernel<<<43776, 256>>>(whh_f, whh_b, bih_f, bhh_f, bih_b, bhh_b,
                                c2_w1, c2_w2, cv_w1, cv_w2);
    prep2_kernel<<<4096, 256>>>(wih_f, wih_b);
    build_seq_kernel<<<dim3(512, 8), 256>>>(x2, x1);

    // rows pass
    gemm_mma_kernel<<<dim3(256, 8), 256, G_SMEM>>>(p_seq);
    lstm_kernel<<<256, 256>>>(0);

    // cols pass
    gemm_mma_kernel<<<dim3(256, 8), 256, G_SMEM>>>(p_rows_hl);
    lstm_kernel<<<256, 256>>>(1);

    // x_site = double_conv(concat([x,x])) via folded weights (A), then c2_w2 (B)
    conv_mma_kernel<<<dim3(256, 2), 256, CONV_SMEM>>>(p_cols, 256, nullptr, 0, WB_A,
                                                      c2_g1, c2_b1, p_hlB, 256, 0);
    conv_mma_kernel<<<dim3(256, 2), 256, CONV_SMEM>>>(p_hlB, 256, nullptr, 0, WB_B,
                                                      c2_g2, c2_b2, p_hlC, 256, 0);
    // x = double_conv(concat([x, x_site]))
    conv_mma_kernel<<<dim3(256, 2), 256, CONV_SMEM>>>(p_cols, 256, p_hlC, 256, WB_C,
                                                      c2_g1, c2_b1, p_hlB, 256, 0);
    conv_mma_kernel<<<dim3(256, 2), 256, CONV_SMEM>>>(p_hlB, 256, nullptr, 0, WB_B,
                                                      c2_g2, c2_b2, p_hlC, 256, 0);
    // final double_conv (cv): 256->128, 128->128 -> d_out (fp32 NCHW)
    conv_mma_kernel<<<dim3(256, 1), 256, CONV_SMEM>>>(p_hlC, 256, nullptr, 0, WB_E,
                                                      cv_g1, cv_b1, p_hlD, 128, 0);
    conv_mma_kernel<<<dim3(256, 1), 256, CONV_SMEM>>>(p_hlD, 128, nullptr, 0, WB_F,
                                                      cv_g2, cv_b2, d_out, 128, 1);
}

// round 15
// speedup vs baseline: 1.4712x; 1.2395x over previous
#include <cuda_runtime.h>
#include <cuda_bf16.h>
#include <cuda_fp16.h>
#include <cstdint>
#include <math.h>

#define EPS_BN 1e-5f

// ===========================================================================
// scratch (device globals)
// ===========================================================================
__device__ uint32_t g_seq [8388608];      // rows-seq hl NHWC
__device__ float    g_xg  [33554432];     // 32768 x 1024 (gate-permuted per dir)
__device__ uint32_t g_rows_hl[8388608];   // rows-LSTM out hl [b][w][h][c]
__device__ uint32_t g_cols_hl[8388608];   // cols-LSTM out NHWC hl
__device__ uint32_t g_hlB[8388608];       // conv temps, NHWC hl
__device__ uint32_t g_hlC[8388608];
__device__ uint32_t g_hlD[4194304];       // 128-channel temp
__device__ __nv_bfloat16 g_wb[11206656];  // conv weights: [ot][tap][cc][pass][k64][n128]
__device__ __nv_bfloat16 g_wih_frag[1048576]; // xg-GEMM B (permuted gates)
__device__ __half   g_whh_h16[2][65536];  // [dir][k*512 + permuted gate], fp16
__device__ float    g_bias2[2][512];      // permuted

// wb region offsets (elements)
#define WB_A 0u
#define WB_B 2359296u
#define WB_C 4718592u
#define WB_E 9437184u
#define WB_F 10616832u

// ===========================================================================
// mma.sync / ldmatrix helpers
// ===========================================================================
__device__ __forceinline__ uint32_t smem_u32(const void* p) {
    uint32_t a;
    asm("{ .reg .u64 t; cvta.to.shared.u64 t, %1; cvt.u32.u64 %0, t; }" : "=r"(a) : "l"(p));
    return a;
}
__device__ __forceinline__ void ldsm4(uint32_t* r, uint32_t addr) {
    asm volatile("ldmatrix.sync.aligned.m8n8.x4.shared.b16 {%0,%1,%2,%3}, [%4];"
        : "=r"(r[0]), "=r"(r[1]), "=r"(r[2]), "=r"(r[3]) : "r"(addr));
}
__device__ __forceinline__ void ldsm4t(uint32_t* r, uint32_t addr) {
    asm volatile("ldmatrix.sync.aligned.m8n8.x4.trans.shared.b16 {%0,%1,%2,%3}, [%4];"
        : "=r"(r[0]), "=r"(r[1]), "=r"(r[2]), "=r"(r[3]) : "r"(addr));
}
__device__ __forceinline__ void mma16816(float* c, const uint32_t* a, uint32_t b0, uint32_t b1) {
    asm volatile("mma.sync.aligned.m16n8k16.row.col.f32.bf16.bf16.f32 "
        "{%0,%1,%2,%3}, {%4,%5,%6,%7}, {%8,%9}, {%0,%1,%2,%3};"
        : "+f"(c[0]), "+f"(c[1]), "+f"(c[2]), "+f"(c[3])
        : "r"(a[0]), "r"(a[1]), "r"(a[2]), "r"(a[3]), "r"(b0), "r"(b1));
}
__device__ __forceinline__ uint32_t hl_pack(float v) {
    __nv_bfloat16 hi = __float2bfloat16(v);
    __nv_bfloat16 lo = __float2bfloat16(v - __bfloat162float(hi));
    return (uint32_t)__bfloat16_as_ushort(hi) | ((uint32_t)__bfloat16_as_ushort(lo) << 16);
}

// ===========================================================================
// prep: Whh fp16 (gate-permuted), bias sums (permuted), conv weight tiles
// permutation: orig gate g = q*128 + cell  ->  pg = cell*4 + q
// ===========================================================================
__global__ void prep_kernel(const float* __restrict__ whh_f, const float* __restrict__ whh_b,
                            const float* __restrict__ bih_f, const float* __restrict__ bhh_f,
                            const float* __restrict__ bih_b, const float* __restrict__ bhh_b,
                            const float* __restrict__ c2w1, const float* __restrict__ c2w2,
                            const float* __restrict__ cvw1, const float* __restrict__ cvw2)
{
    unsigned i = blockIdx.x * 256u + threadIdx.x;
    if (i < 512u * 128u) {
        int g = i / 128, k = i % 128;
        int pg = (g & 127) * 4 + (g >> 7);
        g_whh_h16[0][k * 512 + pg] = __float2half(whh_f[i]);
        g_whh_h16[1][k * 512 + pg] = __float2half(whh_b[i]);
    }
    if (i < 512u) {
        int pg = (i & 127) * 4 + (i >> 7);
        g_bias2[0][pg] = bih_f[i] + bhh_f[i];
        g_bias2[1][pg] = bih_b[i] + bhh_b[i];
    }
    if (i < 11206656u) {
        unsigned l; int CC; int kind;
        if      (i < WB_B) { l = i - WB_A; CC = 8;  kind = 0; }
        else if (i < WB_C) { l = i - WB_B; CC = 8;  kind = 1; }
        else if (i < WB_E) { l = i - WB_C; CC = 16; kind = 2; }
        else if (i < WB_F) { l = i - WB_E; CC = 8;  kind = 3; }
        else               { l = i - WB_F; CC = 4;  kind = 4; }
        int n    = l & 127;
        int k    = (l >> 7) & 63;
        int pass = (l >> 13) & 1;
        unsigned q = l >> 14;
        int cc  = q % CC;  q /= CC;
        int tap = q % 9;   q /= 9;
        int ot  = q;
        int c  = cc * 32 + (k >> 1);
        int oc = ot * 128 + n;
        int odd = k & 1;
        float w;
        if      (kind == 0) w = c2w1[((size_t)oc * 512 + c) * 9 + tap]
                              + c2w1[((size_t)oc * 512 + c + 256) * 9 + tap];
        else if (kind == 1) w = c2w2[((size_t)oc * 256 + c) * 9 + tap];
        else if (kind == 2) w = c2w1[((size_t)oc * 512 + c) * 9 + tap];
        else if (kind == 3) w = cvw1[((size_t)oc * 256 + c) * 9 + tap];
        else                w = cvw2[((size_t)oc * 128 + c) * 9 + tap];
        __nv_bfloat16 hi = __float2bfloat16(w);
        __nv_bfloat16 val;
        if (pass == 0) val = hi;
        else val = odd ? __float2bfloat16(0.f)
                       : __float2bfloat16(w - __bfloat162float(hi));
        g_wb[i] = val;
    }
}

// xg-GEMM B fragments with PERMUTED gate columns
__global__ void prep2_kernel(const float* __restrict__ wih_f,
                             const float* __restrict__ wih_b)
{
    unsigned i = blockIdx.x * 256u + threadIdx.x;
    if (i >= 1048576u) return;
    int n    = i & 127;
    int k    = (i >> 7) & 63;
    int pass = (i >> 13) & 1;
    int cc   = (i >> 14) & 7;
    int nt   = (int)(i >> 17);
    int c    = cc * 32 + (k >> 1);
    int odd  = k & 1;
    const float* W = (nt >= 4) ? wih_b : wih_f;
    int pg   = (nt & 3) * 128 + n;
    int gate = (pg & 3) * 128 + (pg >> 2);
    float w = W[gate * 256 + c];
    __nv_bfloat16 hi = __float2bfloat16(w);
    __nv_bfloat16 val;
    if (pass == 0) val = hi;
    else val = odd ? __float2bfloat16(0.f)
                   : __float2bfloat16(w - __bfloat162float(hi));
    g_wih_frag[i] = val;
}

// ===========================================================================
// build rows-sequence (upsample + concat) -> hl-packed NHWC
// ===========================================================================
__global__ __launch_bounds__(256) void build_seq_kernel(const float* __restrict__ x2,
                                                        const float* __restrict__ x1)
{
    __shared__ float sh[32][65];
    int bh = blockIdx.x;
    int b = bh >> 6, h = bh & 63;
    int ct = blockIdx.y;
    int c0 = ct * 32;
    int tid = threadIdx.x;

    if (ct < 4) {
        for (int idx = tid; idx < 32 * 64; idx += 256) {
            int ci = idx >> 6, w = idx & 63;
            sh[ci][w] = x2[(((size_t)b * 128 + (c0 + ci)) * 64 + h) * 64 + w];
        }
    } else {
        int cc0 = c0 - 128;
        float py = (float)h * 31.0f / 63.0f;
        int yl = (int)floorf(py);
        float wy = py - (float)yl;
        int yh = min(yl + 1, 31);
        for (int idx = tid; idx < 32 * 64; idx += 256) {
            int ci = idx >> 6, w = idx & 63;
            float px = (float)w * 31.0f / 63.0f;
            int xl = (int)floorf(px);
            float wx = px - (float)xl;
            int xh = min(xl + 1, 31);
            const float* base = x1 + ((size_t)b * 128 + (cc0 + ci)) * 1024;
            float v00 = base[yl * 32 + xl], v01 = base[yl * 32 + xh];
            float v10 = base[yh * 32 + xl], v11 = base[yh * 32 + xh];
            float v0 = v00 * (1.f - wx) + v01 * wx;
            float v1 = v10 * (1.f - wx) + v11 * wx;
            sh[ci][w] = v0 * (1.f - wy) + v1 * wy;
        }
    }
    __syncthreads();
    for (int idx = tid; idx < 32 * 64; idx += 256) {
        int w = idx >> 5, cl = idx & 31;
        g_seq[((size_t)bh * 64 + w) * 256 + c0 + cl] = hl_pack(sh[cl][w]);
    }
}

// ===========================================================================
// xg GEMM via mma (A-fragment hoisted across hi/lo passes).
// ===========================================================================
#define GA_BYTES (128 * 144)
#define GB_BYTES (64 * 272)
#define G_SMEM   (GA_BYTES + 2 * GB_BYTES)

__global__ __launch_bounds__(256, 2) void gemm_mma_kernel(const uint32_t* __restrict__ Ahl)
{
    extern __shared__ __align__(16) char smem[];
    char* a_sh = smem;
    char* b_sh = smem + GA_BYTES;

    int tid = threadIdx.x;
    int lane = tid & 31, wid = tid >> 5;
    int warp_m = wid & 3, warp_n = wid >> 2;
    int mbase = blockIdx.x * 128;
    int nt = blockIdx.y;
    int dir = nt >> 2;
    int gbase = (nt & 3) * 128;

    float acc[2][8][4];
#pragma unroll
    for (int m = 0; m < 2; m++)
#pragma unroll
        for (int j = 0; j < 8; j++)
#pragma unroll
            for (int q = 0; q < 4; q++) acc[m][j][q] = 0.f;

    uint32_t a_base = smem_u32(a_sh);
    uint32_t b_base = smem_u32(b_sh);

    int arow = warp_m * 32 + (lane & 7) + ((lane >> 3) & 1) * 8;
    uint32_t a_addr0 = a_base + arow * 144 + ((lane >> 4) * 16);
    int brow = (lane & 7) + ((lane >> 3) & 1) * 8;
    int bcol = warp_n * 64 + ((lane >> 4) * 8);
    uint32_t b_addr0 = b_base + brow * 272 + bcol * 2;

    int s_px = tid >> 1, s_half = tid & 1;

    for (int cc = 0; cc < 8; cc++) {
        {
            const uint4* src = (const uint4*)(Ahl + ((size_t)(mbase + s_px)) * 256 + cc * 32 + s_half * 16);
            uint4* dst = (uint4*)(a_sh + s_px * 144 + s_half * 64);
#pragma unroll
            for (int i = 0; i < 4; i++) dst[i] = src[i];
        }
        const uint4* wsrc = (const uint4*)(g_wih_frag + ((size_t)(nt * 8 + cc)) * 16384u);
#pragma unroll
        for (int i = 0; i < 8; i++) {
            int idx = tid + i * 256;
            int pofs = (idx >= 1024) ? GB_BYTES : 0;
            int li = idx & 1023;
            *(uint4*)(b_sh + pofs + (li >> 4) * 272 + (li & 15) * 16) = wsrc[idx];
        }
        __syncthreads();
#pragma unroll
        for (int ksub = 0; ksub < 4; ksub++) {
            uint32_t a0[4], a1[4];
            ldsm4(a0, a_addr0 + ksub * 32);
            ldsm4(a1, a_addr0 + 16 * 144 + ksub * 32);
#pragma unroll
            for (int pass = 0; pass < 2; pass++) {
                uint32_t bp = b_addr0 + pass * GB_BYTES;
                uint32_t bfr[4][4];
#pragma unroll
                for (int p = 0; p < 4; p++)
                    ldsm4t(bfr[p], bp + ksub * 16 * 272 + p * 32);
#pragma unroll
                for (int j = 0; j < 8; j++) {
                    uint32_t bq0 = bfr[j >> 1][(j & 1) * 2];
                    uint32_t bq1 = bfr[j >> 1][(j & 1) * 2 + 1];
                    mma16816(acc[0][j], a0, bq0, bq1);
                    mma16816(acc[1][j], a1, bq0, bq1);
                }
            }
        }
        __syncthreads();
    }

#pragma unroll
    for (int m = 0; m < 2; m++) {
        int px0 = warp_m * 32 + m * 16 + (lane >> 2);
#pragma unroll
        for (int j = 0; j < 8; j++) {
            int oc = warp_n * 64 + j * 8 + (lane & 3) * 2;
            float b0 = g_bias2[dir][gbase + oc];
            float b1 = g_bias2[dir][gbase + oc + 1];
            size_t col = (size_t)dir * 512 + gbase + oc;
            float* r0 = &g_xg[(size_t)(mbase + px0) * 1024 + col];
            float* r1 = &g_xg[(size_t)(mbase + px0 + 8) * 1024 + col];
            *(float2*)r0 = make_float2(acc[m][j][0] + b0, acc[m][j][1] + b1);
            *(float2*)r1 = make_float2(acc[m][j][2] + b0, acc[m][j][3] + b1);
        }
    }
}

// ===========================================================================
// LSTM recurrence with SM-RESIDENT fp16 weights.
// 128 blocks (dir = blk>>6), 8 seqs/block, 512 threads (16 warps), 1 CTA/SM.
// Weights loaded once into smem (128 KB); recurrence reads smem only.
// thread = 1 cell x 2 seqs; activation in registers; 1 barrier/step.
// ===========================================================================
#define LSTM_W_BYTES 131072
#define LSTM_SMEM    (LSTM_W_BYTES + 2 * 8 * 132 * 4)

__global__ __launch_bounds__(512) void lstm_kernel(int mode)
{
    extern __shared__ __align__(16) char smem[];
    __half* w_sh = (__half*)smem;                         // [128][512]
    float (*h_sh)[8][132] = (float (*)[8][132])(smem + LSTM_W_BYTES);

    int dir = blockIdx.x >> 6;
    int blk = blockIdx.x & 63;
    const float* xg = g_xg + dir * 512;
    uint32_t* out = mode ? g_cols_hl : g_rows_hl;

    int tid = threadIdx.x;

    // load weights once (128 KB, coalesced)
    {
        const uint4* src = (const uint4*)g_whh_h16[dir];
        uint4* dst = (uint4*)w_sh;
        for (int i = tid; i < 8192; i += 512) dst[i] = src[i];
    }

    int ts = tid >> 7;           // 0..3
    int tg = tid & 127;          // cell
    int g0 = tg * 4;
    int sb = ts * 2;             // 2 sequences per thread
    int base_n = blk * 8;

    float c_reg[2] = {0.f, 0.f};
    __syncthreads();

    for (int t = 0; t < 64; t++) {
        int ta = dir ? (63 - t) : t;
        int cur = t & 1, nxt = cur ^ 1;

        // xg loads issued early; latency hides under the k-loop
        float4 x0, x1;
        {
            int n0 = base_n + sb;
            x0 = *(const float4*)&xg[((size_t)n0 * 64 + ta) * 1024 + g0];
            x1 = *(const float4*)&xg[((size_t)(n0 + 1) * 64 + ta) * 1024 + g0];
        }

        float acc[2][4];
#pragma unroll
        for (int si = 0; si < 2; si++)
#pragma unroll
            for (int q = 0; q < 4; q++) acc[si][q] = 0.f;

        if (t > 0) {
#pragma unroll 4
            for (int k = 0; k < 128; k++) {
                uint2 wv = *(const uint2*)&w_sh[k * 512 + g0];
                float2 w01 = __half22float2(*(const __half2*)&wv.x);
                float2 w23 = __half22float2(*(const __half2*)&wv.y);
                float h0 = h_sh[cur][sb + 0][k];
                float h1 = h_sh[cur][sb + 1][k];
                acc[0][0] += h0 * w01.x; acc[0][1] += h0 * w01.y;
                acc[0][2] += h0 * w23.x; acc[0][3] += h0 * w23.y;
                acc[1][0] += h1 * w01.x; acc[1][1] += h1 * w01.y;
                acc[1][2] += h1 * w23.x; acc[1][3] += h1 * w23.y;
            }
        }
        acc[0][0] += x0.x; acc[0][1] += x0.y; acc[0][2] += x0.z; acc[0][3] += x0.w;
        acc[1][0] += x1.x; acc[1][1] += x1.y; acc[1][2] += x1.z; acc[1][3] += x1.w;

#pragma unroll
        for (int si = 0; si < 2; si++) {
            float ig = 1.f / (1.f + expf(-acc[si][0]));
            float fg = 1.f / (1.f + expf(-acc[si][1]));
            float gv = tanhf(acc[si][2]);
            float og = 1.f / (1.f + expf(-acc[si][3]));
            c_reg[si] = fg * c_reg[si] + ig * gv;
            float h = og * tanhf(c_reg[si]);
            h_sh[nxt][sb + si][tg] = h;
            int n = base_n + sb + si;
            int b = n >> 6, loc = n & 63;
            out[(((size_t)(b * 64 + ta)) * 64 + loc) * 256 + dir * 128 + tg] = hl_pack(h);
        }
        __syncthreads();
    }
}

// ===========================================================================
// mma.sync bf16 implicit-GEMM 3x3 conv (R14 version, passing).
// ===========================================================================
#define CONV_A_BYTES   (128 * 144)
#define CONV_B_BYTES   (64 * 272)
#define CONV_SMEM      (CONV_A_BYTES + 2 * CONV_B_BYTES)

__global__ __launch_bounds__(256, 2) void conv_mma_kernel(
    const uint32_t* __restrict__ in0, int C0,
    const uint32_t* __restrict__ in1, int C1,
    unsigned wb_off,
    const float* __restrict__ gamma, const float* __restrict__ beta,
    void* outp, int OC, int final_nchw)
{
    extern __shared__ __align__(16) char smem[];
    char* a_sh = smem;
    char* b_sh = smem + CONV_A_BYTES;
    __shared__ float scs[128], bbs[128];

    int tid = threadIdx.x;
    int lane = tid & 31, wid = tid >> 5;
    int warp_m = wid & 3, warp_n = wid >> 2;
    int bx = blockIdx.x;
    int b = bx >> 5, y0 = (bx & 31) * 2;
    int ot = blockIdx.y, ocb = ot * 128;
    int CIN = C0 + C1, CC = CIN >> 5;

    if (tid < 128) {
        scs[tid] = gamma[ocb + tid] * rsqrtf(1.f + EPS_BN);
        bbs[tid] = beta[ocb + tid];
    }

    float acc[2][8][4];
#pragma unroll
    for (int m = 0; m < 2; m++)
#pragma unroll
        for (int j = 0; j < 8; j++)
#pragma unroll
            for (int q = 0; q < 4; q++) acc[m][j][q] = 0.f;

    uint32_t a_base = smem_u32(a_sh);
    uint32_t b_base = smem_u32(b_sh);

    int arow = warp_m * 32 + (lane & 7) + ((lane >> 3) & 1) * 8;
    uint32_t a_addr0 = a_base + arow * 144 + ((lane >> 4) * 16);
    int brow = (lane & 7) + ((lane >> 3) & 1) * 8;
    int bcol = warp_n * 64 + ((lane >> 4) * 8);
    uint32_t b_addr0 = b_base + brow * 272 + bcol * 2;

    int s_px = tid >> 1, s_half = tid & 1;
    int s_yo = s_px >> 6, s_x = s_px & 63;

    for (int tap = 0; tap < 9; tap++) {
        int ty = tap / 3 - 1, tx = tap % 3 - 1;
        int ys = y0 + s_yo + ty;
        int xs = s_x + tx;
        bool ok = ((unsigned)ys < 64u) && ((unsigned)xs < 64u);
        for (int cc = 0; cc < CC; cc++) {
            {
                int c0 = cc * 32 + s_half * 16;
                const uint4* src;
                if (c0 < C0) src = (const uint4*)(in0 + ((size_t)((b * 64 + ys) * 64 + xs)) * C0 + c0);
                else         src = (const uint4*)(in1 + ((size_t)((b * 64 + ys) * 64 + xs)) * C1 + (c0 - C0));
                uint4* dst = (uint4*)(a_sh + s_px * 144 + s_half * 64);
#pragma unroll
                for (int i = 0; i < 4; i++) {
                    uint4 v = make_uint4(0u, 0u, 0u, 0u);
                    if (ok) v = src[i];
                    dst[i] = v;
                }
            }
            const uint4* wsrc = (const uint4*)(g_wb + wb_off +
                ((size_t)((ot * 9 + tap) * CC + cc)) * 16384u);
#pragma unroll
            for (int i = 0; i < 8; i++) {
                int idx = tid + i * 256;
                int pofs = (idx >= 1024) ? CONV_B_BYTES : 0;
                int li = idx & 1023;
                *(uint4*)(b_sh + pofs + (li >> 4) * 272 + (li & 15) * 16) = wsrc[idx];
            }
            __syncthreads();
#pragma unroll
            for (int ksub = 0; ksub < 4; ksub++) {
                uint32_t a0[4], a1[4];
                ldsm4(a0, a_addr0 + ksub * 32);
                ldsm4(a1, a_addr0 + 16 * 144 + ksub * 32);
#pragma unroll
                for (int pass = 0; pass < 2; pass++) {
                    uint32_t bp = b_addr0 + pass * CONV_B_BYTES;
                    uint32_t bfr[4][4];
#pragma unroll
                    for (int p = 0; p < 4; p++)
                        ldsm4t(bfr[p], bp + ksub * 16 * 272 + p * 32);
#pragma unroll
                    for (int j = 0; j < 8; j++) {
                        uint32_t bq0 = bfr[j >> 1][(j & 1) * 2];
                        uint32_t bq1 = bfr[j >> 1][(j & 1) * 2 + 1];
                        mma16816(acc[0][j], a0, bq0, bq1);
                        mma16816(acc[1][j], a1, bq0, bq1);
                    }
                }
            }
            __syncthreads();
        }
    }

#pragma unroll
    for (int m = 0; m < 2; m++) {
        int px0 = warp_m * 32 + m * 16 + (lane >> 2);
#pragma unroll
        for (int j = 0; j < 8; j++) {
            int oc = warp_n * 64 + j * 8 + (lane & 3) * 2;
            float sc0 = scs[oc], sc1 = scs[oc + 1];
            float bb0 = bbs[oc], bb1 = bbs[oc + 1];
            float v00 = fmaxf(fmaf(acc[m][j][0], sc0, bb0), 0.f);
            float v01 = fmaxf(fmaf(acc[m][j][1], sc1, bb1), 0.f);
            float v10 = fmaxf(fmaf(acc[m][j][2], sc0, bb0), 0.f);
            float v11 = fmaxf(fmaf(acc[m][j][3], sc1, bb1), 0.f);
            if (!final_nchw) {
                uint32_t* out = (uint32_t*)outp;
                size_t base0 = ((size_t)((b * 64 + (y0 + (px0 >> 6))) * 64 + (px0 & 63))) * OC + ocb + oc;
                int px1 = px0 + 8;
                size_t base1 = ((size_t)((b * 64 + (y0 + (px1 >> 6))) * 64 + (px1 & 63))) * OC + ocb + oc;
                *(uint2*)(out + base0) = make_uint2(hl_pack(v00), hl_pack(v01));
                *(uint2*)(out + base1) = make_uint2(hl_pack(v10), hl_pack(v11));
            } else {
                float* out = (float*)outp;
                size_t r0 = ((size_t)b * OC + ocb + oc) * 4096 + y0 * 64;
                size_t r1 = ((size_t)b * OC + ocb + oc + 1) * 4096 + y0 * 64;
                out[r0 + px0] = v00;
                out[r1 + px0] = v01;
                out[r0 + px0 + 8] = v10;
                out[r1 + px0 + 8] = v11;
            }
        }
    }
}

// ===========================================================================
// launcher
// ===========================================================================
extern "C" void kernel_launch(void* const* d_in, const int* in_sizes, int n_in,
                              void* d_out, int out_size)
{
    const float* x1    = (const float*)d_in[0];
    const float* x2    = (const float*)d_in[1];
    const float* wih_f = (const float*)d_in[2];
    const float* whh_f = (const float*)d_in[3];
    const float* bih_f = (const float*)d_in[4];
    const float* bhh_f = (const float*)d_in[5];
    const float* wih_b = (const float*)d_in[6];
    const float* whh_b = (const float*)d_in[7];
    const float* bih_b = (const float*)d_in[8];
    const float* bhh_b = (const float*)d_in[9];
    const float* c2_w1 = (const float*)d_in[10];
    const float* c2_g1 = (const float*)d_in[11];
    const float* c2_b1 = (const float*)d_in[12];
    const float* c2_w2 = (const float*)d_in[13];
    const float* c2_g2 = (const float*)d_in[14];
    const float* c2_b2 = (const float*)d_in[15];
    const float* cv_w1 = (const float*)d_in[16];
    const float* cv_g1 = (const float*)d_in[17];
    const float* cv_b1 = (const float*)d_in[18];
    const float* cv_w2 = (const float*)d_in[19];
    const float* cv_g2 = (const float*)d_in[20];
    const float* cv_b2 = (const float*)d_in[21];

    uint32_t *p_seq = nullptr, *p_rows_hl = nullptr, *p_cols = nullptr,
             *p_hlB = nullptr, *p_hlC = nullptr, *p_hlD = nullptr;
    cudaGetSymbolAddress((void**)&p_seq, g_seq);
    cudaGetSymbolAddress((void**)&p_rows_hl, g_rows_hl);
    cudaGetSymbolAddress((void**)&p_cols, g_cols_hl);
    cudaGetSymbolAddress((void**)&p_hlB, g_hlB);
    cudaGetSymbolAddress((void**)&p_hlC, g_hlC);
    cudaGetSymbolAddress((void**)&p_hlD, g_hlD);

    cudaFuncSetAttribute(conv_mma_kernel,
                         cudaFuncAttributeMaxDynamicSharedMemorySize, CONV_SMEM);
    cudaFuncSetAttribute(gemm_mma_kernel,
                         cudaFuncAttributeMaxDynamicSharedMemorySize, G_SMEM);
    cudaFuncSetAttribute(lstm_kernel,
                         cudaFuncAttributeMaxDynamicSharedMemorySize, LSTM_SMEM);

    prep_kernel<<<43776, 256>>>(whh_f, whh_b, bih_f, bhh_f, bih_b, bhh_b,
                                c2_w1, c2_w2, cv_w1, cv_w2);
    prep2_kernel<<<4096, 256>>>(wih_f, wih_b);
    build_seq_kernel<<<dim3(512, 8), 256>>>(x2, x1);

    // rows pass
    gemm_mma_kernel<<<dim3(256, 8), 256, G_SMEM>>>(p_seq);
    lstm_kernel<<<128, 512, LSTM_SMEM>>>(0);

    // cols pass
    gemm_mma_kernel<<<dim3(256, 8), 256, G_SMEM>>>(p_rows_hl);
    lstm_kernel<<<128, 512, LSTM_SMEM>>>(1);

    // x_site = double_conv(concat([x,x])) via folded weights (A), then c2_w2 (B)
    conv_mma_kernel<<<dim3(256, 2), 256, CONV_SMEM>>>(p_cols, 256, nullptr, 0, WB_A,
                                                      c2_g1, c2_b1, p_hlB, 256, 0);
    conv_mma_kernel<<<dim3(256, 2), 256, CONV_SMEM>>>(p_hlB, 256, nullptr, 0, WB_B,
                                                      c2_g2, c2_b2, p_hlC, 256, 0);
    // x = double_conv(concat([x, x_site]))
    conv_mma_kernel<<<dim3(256, 2), 256, CONV_SMEM>>>(p_cols, 256, p_hlC, 256, WB_C,
                                                      c2_g1, c2_b1, p_hlB, 256, 0);
    conv_mma_kernel<<<dim3(256, 2), 256, CONV_SMEM>>>(p_hlB, 256, nullptr, 0, WB_B,
                                                      c2_g2, c2_b2, p_hlC, 256, 0);
    // final double_conv (cv): 256->128, 128->128 -> d_out (fp32 NCHW)
    conv_mma_kernel<<<dim3(256, 1), 256, CONV_SMEM>>>(p_hlC, 256, nullptr, 0, WB_E,
                                                      cv_g1, cv_b1, p_hlD, 128, 0);
    conv_mma_kernel<<<dim3(256, 1), 256, CONV_SMEM>>>(p_hlD, 128, nullptr, 0, WB_F,
                                                      cv_g2, cv_b2, d_out, 128, 1);
}